// round 9
// baseline (speedup 1.0000x reference)
#include <cuda_runtime.h>
#include <cuda_bf16.h>
#include <cstdint>

// Problem constants
#define N_NODES 50000
#define N_EDGES 800000
#define N_TILES (N_EDGES / 128)     // 6250 exact
#define SPLIT_T 3600                // tensor-path tiles; rest -> FMA path
#define E_SPLIT (SPLIT_T * 128)

// ---------------- scratch (device globals; no allocation allowed) ------------
__device__ int   g_cnt[N_NODES];
__device__ int   g_rowstart[N_NODES + 1];
__device__ int   g_wp[N_NODES];
__device__ int   g_srcs[N_EDGES];          // senders sorted by receiver
__device__ int   g_rcv[N_EDGES];           // receivers sorted (run ids)
__device__ float g_A[N_NODES * 64];        // x @ W1_top + b1
__device__ float g_B[N_NODES * 64];        // x @ W1_bot
__device__ float g_accum[N_NODES * 128];   // segment sums

// ---------------- helpers -----------------------------------------------------
__device__ __forceinline__ uint32_t f2tf32(float x) {
    uint32_t r;
    asm("cvt.rna.tf32.f32 %0, %1;" : "=r"(r) : "f"(x));
    return r;
}
__device__ __forceinline__ void mma_tf32(float* d, const uint32_t* a,
                                         uint32_t b0, uint32_t b1) {
    asm volatile(
        "mma.sync.aligned.m16n8k8.row.col.f32.tf32.tf32.f32 "
        "{%0,%1,%2,%3}, {%4,%5,%6,%7}, {%8,%9}, {%0,%1,%2,%3};"
        : "+f"(d[0]), "+f"(d[1]), "+f"(d[2]), "+f"(d[3])
        : "r"(a[0]), "r"(a[1]), "r"(a[2]), "r"(a[3]), "r"(b0), "r"(b1));
}
__device__ __forceinline__ unsigned long long pk2(float lo, float hi) {
    unsigned long long r;
    asm("mov.b64 %0, {%1, %2};" : "=l"(r)
        : "r"(__float_as_uint(lo)), "r"(__float_as_uint(hi)));
    return r;
}
__device__ __forceinline__ void upk2(unsigned long long v, float& lo, float& hi) {
    unsigned int a, b;
    asm("mov.b64 {%0, %1}, %2;" : "=r"(a), "=r"(b) : "l"(v));
    lo = __uint_as_float(a);
    hi = __uint_as_float(b);
}
#define FMA2(m, a, b) \
    asm("fma.rn.f32x2 %0, %1, %2, %0;" : "+l"(m) : "l"(a), "l"(b))
#define BAR_T() asm volatile("bar.sync 1, 128;" ::: "memory")

// ---------------- CSR construction ------------------------------------------
__global__ void zero_cnt_kernel() {
    int i = blockIdx.x * blockDim.x + threadIdx.x;
    if (i < N_NODES) g_cnt[i] = 0;
}

__global__ void hist_kernel(const int* __restrict__ receivers) {
    int e = blockIdx.x * blockDim.x + threadIdx.x;
    if (e < N_EDGES) atomicAdd(&g_cnt[receivers[e]], 1);
}

__global__ void scan_kernel() {
    __shared__ int wsum[32];
    __shared__ int carry;
    int t = threadIdx.x;
    int lane = t & 31, wid = t >> 5;
    if (t == 0) carry = 0;
    __syncthreads();
    for (int base = 0; base < N_NODES; base += 1024) {
        int i = base + t;
        int v = (i < N_NODES) ? g_cnt[i] : 0;
        int x = v;
#pragma unroll
        for (int o = 1; o < 32; o <<= 1) {
            int y = __shfl_up_sync(0xffffffffu, x, o);
            if (lane >= o) x += y;
        }
        if (lane == 31) wsum[wid] = x;
        __syncthreads();
        if (wid == 0) {
            int s = wsum[lane];
#pragma unroll
            for (int o = 1; o < 32; o <<= 1) {
                int y = __shfl_up_sync(0xffffffffu, s, o);
                if (lane >= o) s += y;
            }
            wsum[lane] = s;
        }
        __syncthreads();
        int excl = carry + (x - v) + (wid > 0 ? wsum[wid - 1] : 0);
        if (i < N_NODES) { g_rowstart[i] = excl; g_wp[i] = excl; }
        __syncthreads();
        if (t == 0) carry += wsum[31];
        __syncthreads();
    }
    if (t == 0) g_rowstart[N_NODES] = carry;
}

__global__ void fill_kernel(const int* __restrict__ senders,
                            const int* __restrict__ receivers) {
    int e = blockIdx.x * blockDim.x + threadIdx.x;
    if (e < N_EDGES) {
        int r = receivers[e];
        int pos = atomicAdd(&g_wp[r], 1);
        g_srcs[pos] = senders[e];
        g_rcv[pos] = r;
    }
}

// ---------------- per-node A/B precompute (FMA2, optional mean-on-read) ------
__global__ __launch_bounds__(128) void node_ab_kernel(
    const float* __restrict__ in, const float* __restrict__ W1,
    const float* __restrict__ b1, float* __restrict__ A, float* __restrict__ B,
    const int* __restrict__ cnt) {
    __shared__ float xs[16][128];
    int t = threadIdx.x;
    int n0 = blockIdx.x * 16;
    {
        const float4* src = (const float4*)(in + (size_t)n0 * 128);
        float4* dst = (float4*)&xs[0][0];
#pragma unroll
        for (int i = 0; i < 4; i++) {
            int idx = t + i * 128;
            float4 v = src[idx];
            if (cnt) {
                int c = cnt[n0 + (idx >> 5)];
                float inv = (c > 0) ? 1.f / (float)c : 0.f;
                v.x *= inv; v.y *= inv; v.z *= inv; v.w *= inv;
            }
            dst[idx] = v;
        }
    }
    __syncthreads();
    int half = t >> 6, j = t & 63;
    const float* Wb = W1 + half * (128 * 64) + j;
    unsigned long long acc2[16];
#pragma unroll
    for (int nn = 0; nn < 16; nn++) acc2[nn] = 0ull;
#pragma unroll 4
    for (int kp = 0; kp < 64; kp++) {
        float w0 = __ldg(Wb + (2 * kp) * 64);
        float w1 = __ldg(Wb + (2 * kp + 1) * 64);
        unsigned long long ww = pk2(w0, w1);
#pragma unroll
        for (int nn = 0; nn < 16; nn++) {
            unsigned long long xx =
                *(const unsigned long long*)&xs[nn][2 * kp];
            FMA2(acc2[nn], ww, xx);
        }
    }
    float binit = half ? 0.f : b1[j];
    float* out = half ? B : A;
#pragma unroll
    for (int nn = 0; nn < 16; nn++) {
        float lo, hi;
        upk2(acc2[nn], lo, hi);
        out[(size_t)(n0 + nn) * 64 + j] = lo + hi + binit;
    }
}

// ---------------- zero accum --------------------------------------------------
__global__ void zero_accum_kernel() {
    int i = blockIdx.x * blockDim.x + threadIdx.x;
    float4* p = (float4*)g_accum;
    if (i < N_NODES * 32) p[i] = make_float4(0.f, 0.f, 0.f, 0.f);
}

// ---------------- FMA-path chunk (from R3) -----------------------------------
template<int EB>
__device__ __forceinline__ void chunkF(
    int e, int e1, const float* __restrict__ B, float a0, float a1, int lane,
    const ulonglong2* __restrict__ W2v, unsigned long long* __restrict__ hw,
    const ulonglong2* __restrict__ hv, float4 bb, float4& acc, bool masked) {
    float r0[EB], r1[EB];
#pragma unroll
    for (int i = 0; i < EB; i++) {
        int ei = e + i;
        int s = g_srcs[(!masked || ei < e1) ? ei : e];
        r0[i] = B[(size_t)s * 64 + lane];
        r1[i] = B[(size_t)s * 64 + 32 + lane];
    }
#pragma unroll
    for (int i = 0; i < EB; i++) {
        float x0 = fmaxf(a0 + r0[i], 0.f);
        float x1 = fmaxf(a1 + r1[i], 0.f);
        hw[i * 64 + lane]      = pk2(x0, x0);
        hw[i * 64 + 32 + lane] = pk2(x1, x1);
    }
    __syncwarp();
    unsigned long long m01[EB], m23[EB];
#pragma unroll
    for (int i = 0; i < EB; i++) { m01[i] = 0ull; m23[i] = 0ull; }
    for (int kk = 0; kk < 32; kk++) {
        ulonglong2 wa = W2v[(2 * kk) * 32 + lane];
        ulonglong2 wb = W2v[(2 * kk + 1) * 32 + lane];
#pragma unroll
        for (int i = 0; i < EB; i++) {
            ulonglong2 hh = hv[i * 32 + kk];
            FMA2(m01[i], wa.x, hh.x);
            FMA2(m23[i], wa.y, hh.x);
            FMA2(m01[i], wb.x, hh.y);
            FMA2(m23[i], wb.y, hh.y);
        }
    }
#pragma unroll
    for (int i = 0; i < EB; i++) {
        if (!masked || e + i < e1) {
            float x0, x1, x2, x3;
            upk2(m01[i], x0, x1);
            upk2(m23[i], x2, x3);
            acc.x += fmaxf(x0 + bb.x, 0.f);
            acc.y += fmaxf(x1 + bb.y, 0.f);
            acc.z += fmaxf(x2 + bb.z, 0.f);
            acc.w += fmaxf(x3 + bb.w, 0.f);
        }
    }
    __syncwarp();
}

// ---------------- hybrid edge kernel -----------------------------------------
// 256 threads. Warps 0-3: tensor path over tiles [0, SPLIT_T) (mma.sync tf32,
// named barrier 1). Warps 4-7: fp32 FMA2 path, warp-per-node over edges
// >= E_SPLIT (warp-private smem, no cross-group sync). Both write sums into
// g_accum (interior runs plain store, boundary/straddle atomicAdd).
// NOTE: SM_RS spans 129 ints (516 B) -> W2F starts at 68736, NOT 68608
// (R6 bug: rs[128] sentinel aliased W2F[0] and NaN-poisoned channel 0).
#define SM_BFRAG 0          // 32768
#define SM_A     32768      // 34816 (aliased by msg 128*66*4)
#define SM_BIAS  67584      // 512
#define SM_RS    68096      // 129 ints = 516 B, ends 68612
#define SM_W2F   68736      // 32768 (16B aligned, clear of rs)
#define SM_HSP   101504     // 32768 (4 F-warps * 1024 ull)
#define SM_TOTAL 134272

__global__ void __launch_bounds__(256, 1) hybrid_edge_kernel(
    const float* __restrict__ Apre, const float* __restrict__ Bpre,
    const float* __restrict__ W2, const float* __restrict__ b2) {
    extern __shared__ char smem[];
    uint32_t* Bfrag = (uint32_t*)(smem + SM_BFRAG);
    float* As   = (float*)(smem + SM_A);
    float* msg  = (float*)(smem + SM_A);
    float* bias = (float*)(smem + SM_BIAS);
    int*   rs   = (int*)(smem + SM_RS);
    int tid = threadIdx.x, w = tid >> 5, lane = tid & 31;

    // setup: Bfrag (tensor operand), W2F copy (FMA operand), bias, sentinel
    for (int idx = tid; idx < 16 * 8 * 32; idx += 256) {
        int nt = idx >> 8;
        int k  = (idx >> 5) & 7;
        int t  = idx & 31;
        int n  = nt * 8 + (t >> 2);
        int kc = k * 8 + (t & 3);
        Bfrag[idx * 2 + 0] = f2tf32(W2[kc * 128 + n]);
        Bfrag[idx * 2 + 1] = f2tf32(W2[(kc + 4) * 128 + n]);
    }
    {
        const float4* src = (const float4*)W2;
        float4* dst = (float4*)(smem + SM_W2F);
        for (int i = tid; i < 2048; i += 256) dst[i] = src[i];
    }
    if (tid < 128) bias[tid] = b2[tid];
    if (tid == 0) rs[128] = -1;
    __syncthreads();

    if (w < 4) {
        // ================= TENSOR PATH (warps 0-3) =================
        const float2* A2 = (const float2*)Apre;
        const float2* B2 = (const float2*)Bpre;
        const uint2*  Bf2 = (const uint2*)Bfrag;
        for (int tile = blockIdx.x; tile < SPLIT_T; tile += gridDim.x) {
            BAR_T();   // prev tile's msg/rs fully consumed
            int e0 = tile * 128;
            int myE = e0 + w * 32 + lane;
            int s_l = g_srcs[myE];
            int r_l = g_rcv[myE];
            rs[w * 32 + lane] = r_l;
#pragma unroll 4
            for (int j = 0; j < 32; j++) {
                int s = __shfl_sync(0xffffffffu, s_l, j);
                int r = __shfl_sync(0xffffffffu, r_l, j);
                float2 va = A2[(size_t)r * 32 + lane];
                float2 vb = B2[(size_t)s * 32 + lane];
                uint32_t t0 = f2tf32(fmaxf(va.x + vb.x, 0.f));
                uint32_t t1 = f2tf32(fmaxf(va.y + vb.y, 0.f));
                *(uint2*)&As[(w * 32 + j) * 68 + 2 * lane] = make_uint2(t0, t1);
            }
            float d[2][16][4];
#pragma unroll
            for (int mt = 0; mt < 2; mt++)
#pragma unroll
                for (int nt = 0; nt < 16; nt++)
#pragma unroll
                    for (int q = 0; q < 4; q++) d[mt][nt][q] = 0.f;
            const uint32_t* abase =
                (const uint32_t*)&As[(w * 32 + (lane >> 2)) * 68 + (lane & 3)];
            for (int k = 0; k < 8; k++) {
                uint32_t a[2][4];
#pragma unroll
                for (int mt = 0; mt < 2; mt++) {
                    const uint32_t* ab = abase + mt * (16 * 68) + k * 8;
                    a[mt][0] = ab[0];
                    a[mt][1] = ab[8 * 68];
                    a[mt][2] = ab[4];
                    a[mt][3] = ab[8 * 68 + 4];
                }
                const uint2* bp = Bf2 + k * 32 + lane;
#pragma unroll
                for (int nt = 0; nt < 16; nt++) {
                    uint2 bb = bp[nt * 256];
                    mma_tf32(d[0][nt], a[0], bb.x, bb.y);
                    mma_tf32(d[1][nt], a[1], bb.x, bb.y);
                }
            }
            BAR_T();   // all T-warps done reading As before msg overwrites
#pragma unroll
            for (int p = 0; p < 2; p++) {
#pragma unroll
                for (int mt = 0; mt < 2; mt++) {
                    int row = w * 32 + mt * 16 + (lane >> 2);
#pragma unroll
                    for (int ntl = 0; ntl < 8; ntl++) {
                        int nt = p * 8 + ntl;
                        int col = nt * 8 + 2 * (lane & 3);
                        int lcol = col - p * 64;
                        float2 bv = *(float2*)&bias[col];
                        float2 v0, v1;
                        v0.x = fmaxf(d[mt][nt][0] + bv.x, 0.f);
                        v0.y = fmaxf(d[mt][nt][1] + bv.y, 0.f);
                        v1.x = fmaxf(d[mt][nt][2] + bv.x, 0.f);
                        v1.y = fmaxf(d[mt][nt][3] + bv.y, 0.f);
                        *(float2*)&msg[row * 66 + lcol] = v0;
                        *(float2*)&msg[(row + 8) * 66 + lcol] = v1;
                    }
                }
                BAR_T();
                {
                    int h = tid >> 6, c = tid & 63;
                    int elo = h * 64, ehi = elo + 64;
                    float s = 0.f;
                    int rstart = elo;
                    int cur = rs[elo];
                    for (int e = elo; e < ehi; e++) {
                        s += msg[e * 66 + c];
                        int nxt = rs[e + 1];     // rs[128] = -1 sentinel
                        bool last = (e == ehi - 1) || (nxt != cur);
                        if (last) {
                            float* dst =
                                &g_accum[(size_t)cur * 128 + p * 64 + c];
                            if (rstart == elo || e == ehi - 1) atomicAdd(dst, s);
                            else *dst = s;
                            s = 0.f;
                            rstart = e + 1;
                            cur = nxt;
                        }
                    }
                }
                if (p == 0) BAR_T();   // before pass1 overwrites msg
            }
        }
    } else {
        // ================= FMA PATH (warps 4-7) =================
        int fw = w - 4;
        unsigned long long* hw =
            (unsigned long long*)(smem + SM_HSP) + fw * 1024;
        const ulonglong2* hv = (const ulonglong2*)hw;
        const ulonglong2* W2v = (const ulonglong2*)(smem + SM_W2F);
        float4 bb = ((const float4*)b2)[lane];
        for (int n = blockIdx.x * 4 + fw; n < N_NODES; n += gridDim.x * 4) {
            int e0 = g_rowstart[n], e1 = g_rowstart[n + 1];
            int es = (e0 > E_SPLIT) ? e0 : E_SPLIT;
            if (es >= e1) continue;
            float a0 = Apre[(size_t)n * 64 + lane];
            float a1 = Apre[(size_t)n * 64 + 32 + lane];
            float4 acc = make_float4(0.f, 0.f, 0.f, 0.f);
            int e = es;
            for (; e + 16 <= e1; e += 16)
                chunkF<16>(e, e1, Bpre, a0, a1, lane, W2v, hw, hv, bb, acc, false);
            for (; e < e1; e += 4)
                chunkF<4>(e, e1, Bpre, a0, a1, lane, W2v, hw, hv, bb, acc, true);
            float* dst = &g_accum[(size_t)n * 128 + lane * 4];
            if (e0 < es) {   // straddles the split: T side also touched it
                atomicAdd(dst + 0, acc.x);
                atomicAdd(dst + 1, acc.y);
                atomicAdd(dst + 2, acc.z);
                atomicAdd(dst + 3, acc.w);
            } else {
                *(float4*)dst = acc;
            }
        }
    }
}

// ---------------- dense tail (mean folded in) ---------------------------------
__global__ __launch_bounds__(256) void tail_kernel(
    const float* __restrict__ h, const float* __restrict__ Wd1,
    const float* __restrict__ bd1, const float* __restrict__ Wd2,
    const float* __restrict__ bd2, float* __restrict__ out,
    const int* __restrict__ cnt) {
    __shared__ float Ws[128 * 64];
    int t = threadIdx.x;
    {
        const float4* src = (const float4*)Wd1;
        float4* dst = (float4*)Ws;
#pragma unroll
        for (int i = 0; i < 8; i++) dst[t + i * 256] = src[t + i * 256];
    }
    __syncthreads();
    int warp = t >> 5, lane = t & 31;
    int n = blockIdx.x * 8 + warp;
    if (n >= N_NODES) return;
    int c = cnt[n];
    float inv = (c > 0) ? 1.f / (float)c : 0.f;
    float x0 = h[(size_t)n * 128 + lane] * inv;
    float x1 = h[(size_t)n * 128 + 32 + lane] * inv;
    float x2 = h[(size_t)n * 128 + 64 + lane] * inv;
    float x3 = h[(size_t)n * 128 + 96 + lane] * inv;
    float g0 = bd1[lane], g1 = bd1[lane + 32];
#pragma unroll
    for (int kk = 0; kk < 32; kk++) {
        float xk;
        xk = __shfl_sync(0xffffffffu, x0, kk);
        g0 = fmaf(xk, Ws[kk * 64 + lane], g0);
        g1 = fmaf(xk, Ws[kk * 64 + lane + 32], g1);
        xk = __shfl_sync(0xffffffffu, x1, kk);
        g0 = fmaf(xk, Ws[(kk + 32) * 64 + lane], g0);
        g1 = fmaf(xk, Ws[(kk + 32) * 64 + lane + 32], g1);
        xk = __shfl_sync(0xffffffffu, x2, kk);
        g0 = fmaf(xk, Ws[(kk + 64) * 64 + lane], g0);
        g1 = fmaf(xk, Ws[(kk + 64) * 64 + lane + 32], g1);
        xk = __shfl_sync(0xffffffffu, x3, kk);
        g0 = fmaf(xk, Ws[(kk + 96) * 64 + lane], g0);
        g1 = fmaf(xk, Ws[(kk + 96) * 64 + lane + 32], g1);
    }
    g0 = fmaxf(g0, 0.f);
    g1 = fmaxf(g1, 0.f);
    float p = g0 * Wd2[lane] + g1 * Wd2[lane + 32];
#pragma unroll
    for (int o = 16; o > 0; o >>= 1) p += __shfl_xor_sync(0xffffffffu, p, o);
    if (lane == 0) out[n] = p + bd2[0];
}

// ---------------- launch ------------------------------------------------------
extern "C" void kernel_launch(void* const* d_in, const int* in_sizes, int n_in,
                              void* d_out, int out_size) {
    const float* x         = (const float*)d_in[0];
    const int*   senders   = (const int*)d_in[1];
    const int*   receivers = (const int*)d_in[2];
    const float* W1a = (const float*)d_in[3];
    const float* b1a = (const float*)d_in[4];
    const float* W2a = (const float*)d_in[5];
    const float* b2a = (const float*)d_in[6];
    const float* W1b = (const float*)d_in[7];
    const float* b1b = (const float*)d_in[8];
    const float* W2b = (const float*)d_in[9];
    const float* b2b = (const float*)d_in[10];
    const float* Wd1 = (const float*)d_in[11];
    const float* bd1 = (const float*)d_in[12];
    const float* Wd2 = (const float*)d_in[13];
    const float* bd2 = (const float*)d_in[14];
    float* out = (float*)d_out;

    static float* pA = nullptr;
    static float* pB = nullptr;
    static float* pAcc = nullptr;
    static int*   pCnt = nullptr;
    static int    nSM = 148;
    if (!pA) {
        cudaGetSymbolAddress((void**)&pA, g_A);
        cudaGetSymbolAddress((void**)&pB, g_B);
        cudaGetSymbolAddress((void**)&pAcc, g_accum);
        cudaGetSymbolAddress((void**)&pCnt, g_cnt);
        cudaFuncSetAttribute(hybrid_edge_kernel,
                             cudaFuncAttributeMaxDynamicSharedMemorySize,
                             SM_TOTAL);
        cudaDeviceProp prop;
        if (cudaGetDeviceProperties(&prop, 0) == cudaSuccess)
            nSM = prop.multiProcessorCount;
    }

    // CSR build
    zero_cnt_kernel<<<(N_NODES + 255) / 256, 256>>>();
    hist_kernel<<<(N_EDGES + 255) / 256, 256>>>(receivers);
    scan_kernel<<<1, 1024>>>();
    fill_kernel<<<(N_EDGES + 255) / 256, 256>>>(senders, receivers);

    // Layer 1
    node_ab_kernel<<<N_NODES / 16, 128>>>(x, W1a, b1a, pA, pB, nullptr);
    zero_accum_kernel<<<(N_NODES * 32 + 255) / 256, 256>>>();
    hybrid_edge_kernel<<<nSM, 256, SM_TOTAL>>>(pA, pB, W2a, b2a);
    // Layer 2 (mean of layer-1 folded into node_ab read)
    node_ab_kernel<<<N_NODES / 16, 128>>>(pAcc, W1b, b1b, pA, pB, pCnt);
    zero_accum_kernel<<<(N_NODES * 32 + 255) / 256, 256>>>();
    hybrid_edge_kernel<<<nSM, 256, SM_TOTAL>>>(pA, pB, W2b, b2b);
    // Dense tail (mean of layer-2 folded in)
    tail_kernel<<<(N_NODES + 7) / 8, 256>>>(pAcc, Wd1, bd1, Wd2, bd2, out, pCnt);
}

// round 10
// speedup vs baseline: 1.4087x; 1.4087x over previous
#include <cuda_runtime.h>
#include <cuda_fp16.h>
#include <cstdint>

// Problem constants
#define N_NODES 50000
#define N_EDGES 800000
#define N_TILES (N_EDGES / 128)     // 6250 exact

// ---------------- scratch (device globals; no allocation allowed) ------------
__device__ int   g_cnt[N_NODES];
__device__ int   g_rowstart[N_NODES + 1];
__device__ int   g_wp[N_NODES];
__device__ int   g_srcs[N_EDGES];          // senders sorted by receiver
__device__ int   g_rcv[N_EDGES];           // receivers sorted (run ids)
__device__ float g_A[N_NODES * 64];        // x @ W1_top + b1
__device__ float g_B[N_NODES * 64];        // x @ W1_bot
__device__ float g_accum[N_NODES * 128];   // segment sums

// ---------------- helpers -----------------------------------------------------
__device__ __forceinline__ uint32_t h2bits(__half2 h) {
    uint32_t u;
    __builtin_memcpy(&u, &h, 4);
    return u;
}
__device__ __forceinline__ void mma_fp16(float* d, const uint32_t* a,
                                         uint32_t b0, uint32_t b1) {
    asm volatile(
        "mma.sync.aligned.m16n8k16.row.col.f32.f16.f16.f32 "
        "{%0,%1,%2,%3}, {%4,%5,%6,%7}, {%8,%9}, {%0,%1,%2,%3};"
        : "+f"(d[0]), "+f"(d[1]), "+f"(d[2]), "+f"(d[3])
        : "r"(a[0]), "r"(a[1]), "r"(a[2]), "r"(a[3]), "r"(b0), "r"(b1));
}
__device__ __forceinline__ unsigned long long pk2(float lo, float hi) {
    unsigned long long r;
    asm("mov.b64 %0, {%1, %2};" : "=l"(r)
        : "r"(__float_as_uint(lo)), "r"(__float_as_uint(hi)));
    return r;
}
__device__ __forceinline__ void upk2(unsigned long long v, float& lo, float& hi) {
    unsigned int a, b;
    asm("mov.b64 {%0, %1}, %2;" : "=r"(a), "=r"(b) : "l"(v));
    lo = __uint_as_float(a);
    hi = __uint_as_float(b);
}
#define FMA2(m, a, b) \
    asm("fma.rn.f32x2 %0, %1, %2, %0;" : "+l"(m) : "l"(a), "l"(b))

// ---------------- CSR construction ------------------------------------------
__global__ void zero_cnt_kernel() {
    int i = blockIdx.x * blockDim.x + threadIdx.x;
    if (i < N_NODES) g_cnt[i] = 0;
}

__global__ void hist_kernel(const int* __restrict__ receivers) {
    int e = blockIdx.x * blockDim.x + threadIdx.x;
    if (e < N_EDGES) atomicAdd(&g_cnt[receivers[e]], 1);
}

__global__ void scan_kernel() {
    __shared__ int wsum[32];
    __shared__ int carry;
    int t = threadIdx.x;
    int lane = t & 31, wid = t >> 5;
    if (t == 0) carry = 0;
    __syncthreads();
    for (int base = 0; base < N_NODES; base += 1024) {
        int i = base + t;
        int v = (i < N_NODES) ? g_cnt[i] : 0;
        int x = v;
#pragma unroll
        for (int o = 1; o < 32; o <<= 1) {
            int y = __shfl_up_sync(0xffffffffu, x, o);
            if (lane >= o) x += y;
        }
        if (lane == 31) wsum[wid] = x;
        __syncthreads();
        if (wid == 0) {
            int s = wsum[lane];
#pragma unroll
            for (int o = 1; o < 32; o <<= 1) {
                int y = __shfl_up_sync(0xffffffffu, s, o);
                if (lane >= o) s += y;
            }
            wsum[lane] = s;
        }
        __syncthreads();
        int excl = carry + (x - v) + (wid > 0 ? wsum[wid - 1] : 0);
        if (i < N_NODES) { g_rowstart[i] = excl; g_wp[i] = excl; }
        __syncthreads();
        if (t == 0) carry += wsum[31];
        __syncthreads();
    }
    if (t == 0) g_rowstart[N_NODES] = carry;
}

__global__ void fill_kernel(const int* __restrict__ senders,
                            const int* __restrict__ receivers) {
    int e = blockIdx.x * blockDim.x + threadIdx.x;
    if (e < N_EDGES) {
        int r = receivers[e];
        int pos = atomicAdd(&g_wp[r], 1);
        g_srcs[pos] = senders[e];
        g_rcv[pos] = r;
    }
}

// ---------------- per-node A/B precompute (FMA2, optional mean-on-read) ------
__global__ __launch_bounds__(128) void node_ab_kernel(
    const float* __restrict__ in, const float* __restrict__ W1,
    const float* __restrict__ b1, float* __restrict__ A, float* __restrict__ B,
    const int* __restrict__ cnt) {
    __shared__ float xs[16][128];
    int t = threadIdx.x;
    int n0 = blockIdx.x * 16;
    {
        const float4* src = (const float4*)(in + (size_t)n0 * 128);
        float4* dst = (float4*)&xs[0][0];
#pragma unroll
        for (int i = 0; i < 4; i++) {
            int idx = t + i * 128;
            float4 v = src[idx];
            if (cnt) {
                int c = cnt[n0 + (idx >> 5)];
                float inv = (c > 0) ? 1.f / (float)c : 0.f;
                v.x *= inv; v.y *= inv; v.z *= inv; v.w *= inv;
            }
            dst[idx] = v;
        }
    }
    __syncthreads();
    int half = t >> 6, j = t & 63;
    const float* Wb = W1 + half * (128 * 64) + j;
    unsigned long long acc2[16];
#pragma unroll
    for (int nn = 0; nn < 16; nn++) acc2[nn] = 0ull;
#pragma unroll 4
    for (int kp = 0; kp < 64; kp++) {
        float w0 = __ldg(Wb + (2 * kp) * 64);
        float w1 = __ldg(Wb + (2 * kp + 1) * 64);
        unsigned long long ww = pk2(w0, w1);
#pragma unroll
        for (int nn = 0; nn < 16; nn++) {
            unsigned long long xx =
                *(const unsigned long long*)&xs[nn][2 * kp];
            FMA2(acc2[nn], ww, xx);
        }
    }
    float binit = half ? 0.f : b1[j];
    float* out = half ? B : A;
#pragma unroll
    for (int nn = 0; nn < 16; nn++) {
        float lo, hi;
        upk2(acc2[nn], lo, hi);
        out[(size_t)(n0 + nn) * 64 + j] = lo + hi + binit;
    }
}

// ---------------- zero accum --------------------------------------------------
__global__ void zero_accum_kernel() {
    int i = blockIdx.x * blockDim.x + threadIdx.x;
    float4* p = (float4*)g_accum;
    if (i < N_NODES * 32) p[i] = make_float4(0.f, 0.f, 0.f, 0.f);
}

// ---------------- tensor-core edge kernel (mma.sync fp16 m16n8k16) ----------
// Tile = 128 edges (M=128), K=64, N=128. Block = 4 warps; warp w owns rows
// [32w,32w+32). A (fp16 pairs) in smem row-stride 36 b32 (bank = 4g+ti ->
// conflict-free frag loads). W2 pre-packed fp16 fragment-ordered (uint2 loads,
// conflict-free). 4 k-steps x 16 n-tiles x 2 m-tiles = 128 mma/warp/tile.
// Epilogue in two 64-col passes over msg aliasing the A tile; receiver-sorted
// segmented reduce (interior runs plain store, boundary runs atomicAdd).
#define SM_BFRAG 0          // 2048 uint2 = 16384 B
#define SM_A     16384      // A: 128*36*4 = 18432 B; msg alias: 128*66*4 = 33792 B
#define SM_BIAS  50176      // 512 B
#define SM_RS    50688      // 129 ints = 516 B, ends 51204
#define SM_TOTAL 51456

__global__ void __launch_bounds__(128, 2) edge_mma_kernel(
    const float* __restrict__ Apre, const float* __restrict__ Bpre,
    const float* __restrict__ W2, const float* __restrict__ b2) {
    extern __shared__ char smem[];
    uint32_t* Bfrag = (uint32_t*)(smem + SM_BFRAG);
    uint32_t* As16  = (uint32_t*)(smem + SM_A);
    float* msg  = (float*)(smem + SM_A);
    float* bias = (float*)(smem + SM_BIAS);
    int*   rs   = (int*)(smem + SM_RS);
    int tid = threadIdx.x, w = tid >> 5, lane = tid & 31;

    // Pack W2 (K=64 x N=128) into fp16 fragment order.
    // entry idx: nt = idx>>7, ks = (idx>>5)&3, t = idx&31, g = t>>2, ti = t&3
    // b0 = {W2[k0+2ti][n], W2[k0+2ti+1][n]}, b1 = {W2[k0+8+2ti][n], W2[k0+9+2ti][n]}
    for (int idx = tid; idx < 2048; idx += 128) {
        int nt = idx >> 7;
        int ks = (idx >> 5) & 3;
        int t  = idx & 31;
        int n  = nt * 8 + (t >> 2);
        int k0 = ks * 16 + 2 * (t & 3);
        __half2 p0 = __floats2half2_rn(W2[k0 * 128 + n], W2[(k0 + 1) * 128 + n]);
        __half2 p1 = __floats2half2_rn(W2[(k0 + 8) * 128 + n], W2[(k0 + 9) * 128 + n]);
        Bfrag[idx * 2 + 0] = h2bits(p0);
        Bfrag[idx * 2 + 1] = h2bits(p1);
    }
    bias[tid] = b2[tid];
    if (tid == 0) rs[128] = -1;
    __syncthreads();

    const float2* A2 = (const float2*)Apre;
    const float2* B2 = (const float2*)Bpre;
    const uint2*  Bf2 = (const uint2*)Bfrag;

    for (int tile = blockIdx.x; tile < N_TILES; tile += gridDim.x) {
        __syncthreads();   // prev tile's msg/rs fully consumed
        int e0 = tile * 128;
        // ---- build A rows (warp-private rows; no sync needed before MMA)
        int myE = e0 + w * 32 + lane;
        int s_l = g_srcs[myE];
        int r_l = g_rcv[myE];
        rs[w * 32 + lane] = r_l;
#pragma unroll 4
        for (int j = 0; j < 32; j++) {
            int s = __shfl_sync(0xffffffffu, s_l, j);
            int r = __shfl_sync(0xffffffffu, r_l, j);
            float2 va = A2[(size_t)r * 32 + lane];
            float2 vb = B2[(size_t)s * 32 + lane];
            __half2 h = __floats2half2_rn(fmaxf(va.x + vb.x, 0.f),
                                          fmaxf(va.y + vb.y, 0.f));
            As16[(w * 32 + j) * 36 + lane] = h2bits(h);
        }
        // ---- MMA: D[2 mtiles][16 ntiles][4], 4 k-steps of 16
        float d[2][16][4];
#pragma unroll
        for (int mt = 0; mt < 2; mt++)
#pragma unroll
            for (int nt = 0; nt < 16; nt++)
#pragma unroll
                for (int q = 0; q < 4; q++) d[mt][nt][q] = 0.f;
        const uint32_t* abase =
            As16 + (w * 32 + (lane >> 2)) * 36 + (lane & 3);
        for (int ks = 0; ks < 4; ks++) {
            uint32_t a[2][4];
#pragma unroll
            for (int mt = 0; mt < 2; mt++) {
                const uint32_t* ab = abase + mt * (16 * 36) + ks * 8;
                a[mt][0] = ab[0];
                a[mt][1] = ab[8 * 36];
                a[mt][2] = ab[4];
                a[mt][3] = ab[8 * 36 + 4];
            }
            const uint2* bp = Bf2 + ks * 32 + lane;
#pragma unroll
            for (int nt = 0; nt < 16; nt++) {
                uint2 bb = bp[nt * 128];
                mma_fp16(d[0][nt], a[0], bb.x, bb.y);
                mma_fp16(d[1][nt], a[1], bb.x, bb.y);
            }
        }
        __syncthreads();   // all warps done reading As before msg overwrites
        // ---- two epilogue+reduce passes (cols [0,64) then [64,128))
#pragma unroll
        for (int p = 0; p < 2; p++) {
#pragma unroll
            for (int mt = 0; mt < 2; mt++) {
                int row = w * 32 + mt * 16 + (lane >> 2);
#pragma unroll
                for (int ntl = 0; ntl < 8; ntl++) {
                    int nt = p * 8 + ntl;
                    int col = nt * 8 + 2 * (lane & 3);
                    int lcol = col - p * 64;
                    float2 bv = *(float2*)&bias[col];
                    float2 v0, v1;
                    v0.x = fmaxf(d[mt][nt][0] + bv.x, 0.f);
                    v0.y = fmaxf(d[mt][nt][1] + bv.y, 0.f);
                    v1.x = fmaxf(d[mt][nt][2] + bv.x, 0.f);
                    v1.y = fmaxf(d[mt][nt][3] + bv.y, 0.f);
                    *(float2*)&msg[row * 66 + lcol] = v0;
                    *(float2*)&msg[(row + 8) * 66 + lcol] = v1;
                }
            }
            __syncthreads();
            // segmented reduce: thread = (row-half, channel)
            {
                int h = tid >> 6, c = tid & 63;
                int elo = h * 64, ehi = elo + 64;
                float s = 0.f;
                int rstart = elo;
                int cur = rs[elo];
                for (int e = elo; e < ehi; e++) {
                    s += msg[e * 66 + c];
                    int nxt = rs[e + 1];     // rs[128] = -1 sentinel
                    bool last = (e == ehi - 1) || (nxt != cur);
                    if (last) {
                        float* dst = &g_accum[(size_t)cur * 128 + p * 64 + c];
                        if (rstart == elo || e == ehi - 1) atomicAdd(dst, s);
                        else *dst = s;
                        s = 0.f;
                        rstart = e + 1;
                        cur = nxt;
                    }
                }
            }
            if (p == 0) __syncthreads();   // before pass1 overwrites msg
        }
    }
}

// ---------------- dense tail (mean folded in) ---------------------------------
__global__ __launch_bounds__(256) void tail_kernel(
    const float* __restrict__ h, const float* __restrict__ Wd1,
    const float* __restrict__ bd1, const float* __restrict__ Wd2,
    const float* __restrict__ bd2, float* __restrict__ out,
    const int* __restrict__ cnt) {
    __shared__ float Ws[128 * 64];
    int t = threadIdx.x;
    {
        const float4* src = (const float4*)Wd1;
        float4* dst = (float4*)Ws;
#pragma unroll
        for (int i = 0; i < 8; i++) dst[t + i * 256] = src[t + i * 256];
    }
    __syncthreads();
    int warp = t >> 5, lane = t & 31;
    int n = blockIdx.x * 8 + warp;
    if (n >= N_NODES) return;
    int c = cnt[n];
    float inv = (c > 0) ? 1.f / (float)c : 0.f;
    float x0 = h[(size_t)n * 128 + lane] * inv;
    float x1 = h[(size_t)n * 128 + 32 + lane] * inv;
    float x2 = h[(size_t)n * 128 + 64 + lane] * inv;
    float x3 = h[(size_t)n * 128 + 96 + lane] * inv;
    float g0 = bd1[lane], g1 = bd1[lane + 32];
#pragma unroll
    for (int kk = 0; kk < 32; kk++) {
        float xk;
        xk = __shfl_sync(0xffffffffu, x0, kk);
        g0 = fmaf(xk, Ws[kk * 64 + lane], g0);
        g1 = fmaf(xk, Ws[kk * 64 + lane + 32], g1);
        xk = __shfl_sync(0xffffffffu, x1, kk);
        g0 = fmaf(xk, Ws[(kk + 32) * 64 + lane], g0);
        g1 = fmaf(xk, Ws[(kk + 32) * 64 + lane + 32], g1);
        xk = __shfl_sync(0xffffffffu, x2, kk);
        g0 = fmaf(xk, Ws[(kk + 64) * 64 + lane], g0);
        g1 = fmaf(xk, Ws[(kk + 64) * 64 + lane + 32], g1);
        xk = __shfl_sync(0xffffffffu, x3, kk);
        g0 = fmaf(xk, Ws[(kk + 96) * 64 + lane], g0);
        g1 = fmaf(xk, Ws[(kk + 96) * 64 + lane + 32], g1);
    }
    g0 = fmaxf(g0, 0.f);
    g1 = fmaxf(g1, 0.f);
    float p = g0 * Wd2[lane] + g1 * Wd2[lane + 32];
#pragma unroll
    for (int o = 16; o > 0; o >>= 1) p += __shfl_xor_sync(0xffffffffu, p, o);
    if (lane == 0) out[n] = p + bd2[0];
}

// ---------------- launch ------------------------------------------------------
extern "C" void kernel_launch(void* const* d_in, const int* in_sizes, int n_in,
                              void* d_out, int out_size) {
    const float* x         = (const float*)d_in[0];
    const int*   senders   = (const int*)d_in[1];
    const int*   receivers = (const int*)d_in[2];
    const float* W1a = (const float*)d_in[3];
    const float* b1a = (const float*)d_in[4];
    const float* W2a = (const float*)d_in[5];
    const float* b2a = (const float*)d_in[6];
    const float* W1b = (const float*)d_in[7];
    const float* b1b = (const float*)d_in[8];
    const float* W2b = (const float*)d_in[9];
    const float* b2b = (const float*)d_in[10];
    const float* Wd1 = (const float*)d_in[11];
    const float* bd1 = (const float*)d_in[12];
    const float* Wd2 = (const float*)d_in[13];
    const float* bd2 = (const float*)d_in[14];
    float* out = (float*)d_out;

    static float* pA = nullptr;
    static float* pB = nullptr;
    static float* pAcc = nullptr;
    static int*   pCnt = nullptr;
    static int    nSM = 148;
    if (!pA) {
        cudaGetSymbolAddress((void**)&pA, g_A);
        cudaGetSymbolAddress((void**)&pB, g_B);
        cudaGetSymbolAddress((void**)&pAcc, g_accum);
        cudaGetSymbolAddress((void**)&pCnt, g_cnt);
        cudaFuncSetAttribute(edge_mma_kernel,
                             cudaFuncAttributeMaxDynamicSharedMemorySize,
                             SM_TOTAL);
        cudaDeviceProp prop;
        if (cudaGetDeviceProperties(&prop, 0) == cudaSuccess)
            nSM = prop.multiProcessorCount;
    }

    // CSR build
    zero_cnt_kernel<<<(N_NODES + 255) / 256, 256>>>();
    hist_kernel<<<(N_EDGES + 255) / 256, 256>>>(receivers);
    scan_kernel<<<1, 1024>>>();
    fill_kernel<<<(N_EDGES + 255) / 256, 256>>>(senders, receivers);

    int mmaBlocks = 2 * nSM;

    // Layer 1
    node_ab_kernel<<<N_NODES / 16, 128>>>(x, W1a, b1a, pA, pB, nullptr);
    zero_accum_kernel<<<(N_NODES * 32 + 255) / 256, 256>>>();
    edge_mma_kernel<<<mmaBlocks, 128, SM_TOTAL>>>(pA, pB, W2a, b2a);
    // Layer 2 (mean of layer-1 folded into node_ab read)
    node_ab_kernel<<<N_NODES / 16, 128>>>(pAcc, W1b, b1b, pA, pB, pCnt);
    zero_accum_kernel<<<(N_NODES * 32 + 255) / 256, 256>>>();
    edge_mma_kernel<<<mmaBlocks, 128, SM_TOTAL>>>(pA, pB, W2b, b2b);
    // Dense tail (mean of layer-2 folded in)
    tail_kernel<<<(N_NODES + 7) / 8, 256>>>(pAcc, Wd1, bd1, Wd2, bd2, out, pCnt);
}

// round 11
// speedup vs baseline: 1.8133x; 1.2872x over previous
#include <cuda_runtime.h>
#include <cuda_fp16.h>
#include <cstdint>

// Problem constants
#define N_NODES 50000
#define N_EDGES 800000
#define N_TILES (N_EDGES / 128)     // 6250 exact

// ---------------- scratch (device globals; no allocation allowed) ------------
__device__ int   g_cnt[N_NODES];
__device__ int   g_rowstart[N_NODES + 1];
__device__ int   g_wp[N_NODES];
__device__ int   g_srcs[N_EDGES];          // senders sorted by receiver
__device__ int   g_rcv[N_EDGES];           // receivers sorted (run ids)
__device__ float g_A[N_NODES * 64];        // x @ W1_top + b1
__device__ float g_B[N_NODES * 64];        // x @ W1_bot
__device__ float g_accum[N_NODES * 128];   // segment sums

// ---------------- helpers -----------------------------------------------------
__device__ __forceinline__ uint32_t h2bits(__half2 h) {
    uint32_t u;
    __builtin_memcpy(&u, &h, 4);
    return u;
}
__device__ __forceinline__ void mma_fp16(float* d, const uint32_t* a,
                                         uint32_t b0, uint32_t b1) {
    asm volatile(
        "mma.sync.aligned.m16n8k16.row.col.f32.f16.f16.f32 "
        "{%0,%1,%2,%3}, {%4,%5,%6,%7}, {%8,%9}, {%0,%1,%2,%3};"
        : "+f"(d[0]), "+f"(d[1]), "+f"(d[2]), "+f"(d[3])
        : "r"(a[0]), "r"(a[1]), "r"(a[2]), "r"(a[3]), "r"(b0), "r"(b1));
}
__device__ __forceinline__ unsigned long long pk2(float lo, float hi) {
    unsigned long long r;
    asm("mov.b64 %0, {%1, %2};" : "=l"(r)
        : "r"(__float_as_uint(lo)), "r"(__float_as_uint(hi)));
    return r;
}
__device__ __forceinline__ void upk2(unsigned long long v, float& lo, float& hi) {
    unsigned int a, b;
    asm("mov.b64 {%0, %1}, %2;" : "=r"(a), "=r"(b) : "l"(v));
    lo = __uint_as_float(a);
    hi = __uint_as_float(b);
}
#define FMA2(m, a, b) \
    asm("fma.rn.f32x2 %0, %1, %2, %0;" : "+l"(m) : "l"(a), "l"(b))

// ---------------- CSR construction ------------------------------------------
__global__ void zero_cnt_kernel() {
    int i = blockIdx.x * blockDim.x + threadIdx.x;
    if (i < N_NODES) g_cnt[i] = 0;
}

__global__ void hist_kernel(const int* __restrict__ receivers) {
    int e = blockIdx.x * blockDim.x + threadIdx.x;
    if (e < N_EDGES) atomicAdd(&g_cnt[receivers[e]], 1);
}

__global__ void scan_kernel() {
    __shared__ int wsum[32];
    __shared__ int carry;
    int t = threadIdx.x;
    int lane = t & 31, wid = t >> 5;
    if (t == 0) carry = 0;
    __syncthreads();
    for (int base = 0; base < N_NODES; base += 1024) {
        int i = base + t;
        int v = (i < N_NODES) ? g_cnt[i] : 0;
        int x = v;
#pragma unroll
        for (int o = 1; o < 32; o <<= 1) {
            int y = __shfl_up_sync(0xffffffffu, x, o);
            if (lane >= o) x += y;
        }
        if (lane == 31) wsum[wid] = x;
        __syncthreads();
        if (wid == 0) {
            int s = wsum[lane];
#pragma unroll
            for (int o = 1; o < 32; o <<= 1) {
                int y = __shfl_up_sync(0xffffffffu, s, o);
                if (lane >= o) s += y;
            }
            wsum[lane] = s;
        }
        __syncthreads();
        int excl = carry + (x - v) + (wid > 0 ? wsum[wid - 1] : 0);
        if (i < N_NODES) { g_rowstart[i] = excl; g_wp[i] = excl; }
        __syncthreads();
        if (t == 0) carry += wsum[31];
        __syncthreads();
    }
    if (t == 0) g_rowstart[N_NODES] = carry;
}

__global__ void fill_kernel(const int* __restrict__ senders,
                            const int* __restrict__ receivers) {
    int e = blockIdx.x * blockDim.x + threadIdx.x;
    if (e < N_EDGES) {
        int r = receivers[e];
        int pos = atomicAdd(&g_wp[r], 1);
        g_srcs[pos] = senders[e];
        g_rcv[pos] = r;
    }
}

// ---------------- per-node A/B precompute (FMA2, optional mean-on-read) ------
__global__ __launch_bounds__(128) void node_ab_kernel(
    const float* __restrict__ in, const float* __restrict__ W1,
    const float* __restrict__ b1, float* __restrict__ A, float* __restrict__ B,
    const int* __restrict__ cnt) {
    __shared__ float xs[16][128];
    int t = threadIdx.x;
    int n0 = blockIdx.x * 16;
    {
        const float4* src = (const float4*)(in + (size_t)n0 * 128);
        float4* dst = (float4*)&xs[0][0];
#pragma unroll
        for (int i = 0; i < 4; i++) {
            int idx = t + i * 128;
            float4 v = src[idx];
            if (cnt) {
                int c = cnt[n0 + (idx >> 5)];
                float inv = (c > 0) ? 1.f / (float)c : 0.f;
                v.x *= inv; v.y *= inv; v.z *= inv; v.w *= inv;
            }
            dst[idx] = v;
        }
    }
    __syncthreads();
    int half = t >> 6, j = t & 63;
    const float* Wb = W1 + half * (128 * 64) + j;
    unsigned long long acc2[16];
#pragma unroll
    for (int nn = 0; nn < 16; nn++) acc2[nn] = 0ull;
#pragma unroll 4
    for (int kp = 0; kp < 64; kp++) {
        float w0 = __ldg(Wb + (2 * kp) * 64);
        float w1 = __ldg(Wb + (2 * kp + 1) * 64);
        unsigned long long ww = pk2(w0, w1);
#pragma unroll
        for (int nn = 0; nn < 16; nn++) {
            unsigned long long xx =
                *(const unsigned long long*)&xs[nn][2 * kp];
            FMA2(acc2[nn], ww, xx);
        }
    }
    float binit = half ? 0.f : b1[j];
    float* out = half ? B : A;
#pragma unroll
    for (int nn = 0; nn < 16; nn++) {
        float lo, hi;
        upk2(acc2[nn], lo, hi);
        out[(size_t)(n0 + nn) * 64 + j] = lo + hi + binit;
    }
}

// ---------------- zero accum --------------------------------------------------
__global__ void zero_accum_kernel() {
    int i = blockIdx.x * blockDim.x + threadIdx.x;
    float4* p = (float4*)g_accum;
    if (i < N_NODES * 32) p[i] = make_float4(0.f, 0.f, 0.f, 0.f);
}

// ---------------- tensor-core edge kernel (fp16 m16n8k16, 8 warps) ----------
// Tile = 128 edges (M=128), K=64, N=128. Block = 8 warps, 256 threads.
// Warp w: row-group wr = w>>1 owns rows [32wr,32wr+32); col-half w2 = w&1 owns
// cols [64*w2, 64*w2+64). Each warp: 16-row A build (8-row batched gathers),
// 64 mma, d = 64 regs. Single-pass epilogue into full-width msg[128][132]
// (aliases A tile), then one 64-long segmented reduce (128 channels x 2
// row-halves over 256 threads). Interior runs plain store, boundary atomics.
#define SM_BFRAG 0          // 2048 uint2 = 16384 B
#define SM_A     16384      // A: 128*36*4 = 18432 B; msg alias: 128*132*4 = 67584 B
#define SM_BIAS  83968      // 512 B
#define SM_RS    84480      // 129 ints = 516 B, ends 84996
#define SM_TOTAL 85120

__global__ void __launch_bounds__(256, 2) edge_mma_kernel(
    const float* __restrict__ Apre, const float* __restrict__ Bpre,
    const float* __restrict__ W2, const float* __restrict__ b2) {
    extern __shared__ char smem[];
    uint32_t* Bfrag = (uint32_t*)(smem + SM_BFRAG);
    uint32_t* As16  = (uint32_t*)(smem + SM_A);
    float* msg  = (float*)(smem + SM_A);
    float* bias = (float*)(smem + SM_BIAS);
    int*   rs   = (int*)(smem + SM_RS);
    int tid = threadIdx.x, w = tid >> 5, lane = tid & 31;
    int wr = w >> 1, w2 = w & 1;

    // Pack W2 (K=64 x N=128) into fp16 fragment order.
    for (int idx = tid; idx < 2048; idx += 256) {
        int nt = idx >> 7;
        int ks = (idx >> 5) & 3;
        int t  = idx & 31;
        int n  = nt * 8 + (t >> 2);
        int k0 = ks * 16 + 2 * (t & 3);
        __half2 p0 = __floats2half2_rn(W2[k0 * 128 + n], W2[(k0 + 1) * 128 + n]);
        __half2 p1 = __floats2half2_rn(W2[(k0 + 8) * 128 + n], W2[(k0 + 9) * 128 + n]);
        Bfrag[idx * 2 + 0] = h2bits(p0);
        Bfrag[idx * 2 + 1] = h2bits(p1);
    }
    if (tid < 128) bias[tid] = b2[tid];
    if (tid == 0) rs[128] = -1;
    __syncthreads();

    const float2* A2 = (const float2*)Apre;
    const float2* B2 = (const float2*)Bpre;
    const uint2*  Bf2 = (const uint2*)Bfrag;

    for (int tile = blockIdx.x; tile < N_TILES; tile += gridDim.x) {
        __syncthreads();   // prev tile's msg/rs fully consumed
        int e0 = tile * 128;
        // ---- build A: warp w builds rows [16w, 16w+16), batched gathers
        int base_e = e0 + w * 16;
        int s_l = g_srcs[base_e + (lane & 15)];
        int r_l = g_rcv[base_e + (lane & 15)];
        if (lane < 16) rs[w * 16 + lane] = r_l;
#pragma unroll
        for (int jb = 0; jb < 16; jb += 8) {
            float2 va[8], vb[8];
#pragma unroll
            for (int j = 0; j < 8; j++) {
                int s = __shfl_sync(0xffffffffu, s_l, jb + j);
                int r = __shfl_sync(0xffffffffu, r_l, jb + j);
                va[j] = A2[(size_t)r * 32 + lane];
                vb[j] = B2[(size_t)s * 32 + lane];
            }
#pragma unroll
            for (int j = 0; j < 8; j++) {
                __half2 h = __floats2half2_rn(fmaxf(va[j].x + vb[j].x, 0.f),
                                              fmaxf(va[j].y + vb[j].y, 0.f));
                As16[(w * 16 + jb + j) * 36 + lane] = h2bits(h);
            }
        }
        __syncthreads();   // all rows built before cross-warp frag reads
        // ---- MMA: warp does rows [32wr,+32) x cols [64w2,+64)
        float d[2][8][4];
#pragma unroll
        for (int mt = 0; mt < 2; mt++)
#pragma unroll
            for (int nt = 0; nt < 8; nt++)
#pragma unroll
                for (int q = 0; q < 4; q++) d[mt][nt][q] = 0.f;
        const uint32_t* abase =
            As16 + (wr * 32 + (lane >> 2)) * 36 + (lane & 3);
        for (int ks = 0; ks < 4; ks++) {
            uint32_t a[2][4];
#pragma unroll
            for (int mt = 0; mt < 2; mt++) {
                const uint32_t* ab = abase + mt * (16 * 36) + ks * 8;
                a[mt][0] = ab[0];
                a[mt][1] = ab[8 * 36];
                a[mt][2] = ab[4];
                a[mt][3] = ab[8 * 36 + 4];
            }
            const uint2* bp = Bf2 + ks * 32 + lane;
#pragma unroll
            for (int ntl = 0; ntl < 8; ntl++) {
                uint2 bb = bp[(w2 * 8 + ntl) * 128];
                mma_fp16(d[0][ntl], a[0], bb.x, bb.y);
                mma_fp16(d[1][ntl], a[1], bb.x, bb.y);
            }
        }
        __syncthreads();   // all warps done reading As before msg overwrites
        // ---- single-pass epilogue: relu(+bias) -> msg[128][132]
#pragma unroll
        for (int mt = 0; mt < 2; mt++) {
            int row = wr * 32 + mt * 16 + (lane >> 2);
#pragma unroll
            for (int ntl = 0; ntl < 8; ntl++) {
                int col = (w2 * 8 + ntl) * 8 + 2 * (lane & 3);
                float2 bv = *(float2*)&bias[col];
                float2 v0, v1;
                v0.x = fmaxf(d[mt][ntl][0] + bv.x, 0.f);
                v0.y = fmaxf(d[mt][ntl][1] + bv.y, 0.f);
                v1.x = fmaxf(d[mt][ntl][2] + bv.x, 0.f);
                v1.y = fmaxf(d[mt][ntl][3] + bv.y, 0.f);
                *(float2*)&msg[row * 132 + col] = v0;
                *(float2*)&msg[(row + 8) * 132 + col] = v1;
            }
        }
        __syncthreads();
        // ---- segmented reduce: 256 threads = 128 channels x 2 row-halves
        {
            int c = tid & 127, h = tid >> 7;
            int elo = h * 64, ehi = elo + 64;
            float s = 0.f;
            int rstart = elo;
            int cur = rs[elo];
            for (int e = elo; e < ehi; e++) {
                s += msg[e * 132 + c];
                int nxt = rs[e + 1];     // rs[128] = -1 sentinel
                bool last = (e == ehi - 1) || (nxt != cur);
                if (last) {
                    float* dst = &g_accum[(size_t)cur * 128 + c];
                    if (rstart == elo || e == ehi - 1) atomicAdd(dst, s);
                    else *dst = s;
                    s = 0.f;
                    rstart = e + 1;
                    cur = nxt;
                }
            }
        }
    }
}

// ---------------- dense tail (mean folded in) ---------------------------------
__global__ __launch_bounds__(256) void tail_kernel(
    const float* __restrict__ h, const float* __restrict__ Wd1,
    const float* __restrict__ bd1, const float* __restrict__ Wd2,
    const float* __restrict__ bd2, float* __restrict__ out,
    const int* __restrict__ cnt) {
    __shared__ float Ws[128 * 64];
    int t = threadIdx.x;
    {
        const float4* src = (const float4*)Wd1;
        float4* dst = (float4*)Ws;
#pragma unroll
        for (int i = 0; i < 8; i++) dst[t + i * 256] = src[t + i * 256];
    }
    __syncthreads();
    int warp = t >> 5, lane = t & 31;
    int n = blockIdx.x * 8 + warp;
    if (n >= N_NODES) return;
    int c = cnt[n];
    float inv = (c > 0) ? 1.f / (float)c : 0.f;
    float x0 = h[(size_t)n * 128 + lane] * inv;
    float x1 = h[(size_t)n * 128 + 32 + lane] * inv;
    float x2 = h[(size_t)n * 128 + 64 + lane] * inv;
    float x3 = h[(size_t)n * 128 + 96 + lane] * inv;
    float g0 = bd1[lane], g1 = bd1[lane + 32];
#pragma unroll
    for (int kk = 0; kk < 32; kk++) {
        float xk;
        xk = __shfl_sync(0xffffffffu, x0, kk);
        g0 = fmaf(xk, Ws[kk * 64 + lane], g0);
        g1 = fmaf(xk, Ws[kk * 64 + lane + 32], g1);
        xk = __shfl_sync(0xffffffffu, x1, kk);
        g0 = fmaf(xk, Ws[(kk + 32) * 64 + lane], g0);
        g1 = fmaf(xk, Ws[(kk + 32) * 64 + lane + 32], g1);
        xk = __shfl_sync(0xffffffffu, x2, kk);
        g0 = fmaf(xk, Ws[(kk + 64) * 64 + lane], g0);
        g1 = fmaf(xk, Ws[(kk + 64) * 64 + lane + 32], g1);
        xk = __shfl_sync(0xffffffffu, x3, kk);
        g0 = fmaf(xk, Ws[(kk + 96) * 64 + lane], g0);
        g1 = fmaf(xk, Ws[(kk + 96) * 64 + lane + 32], g1);
    }
    g0 = fmaxf(g0, 0.f);
    g1 = fmaxf(g1, 0.f);
    float p = g0 * Wd2[lane] + g1 * Wd2[lane + 32];
#pragma unroll
    for (int o = 16; o > 0; o >>= 1) p += __shfl_xor_sync(0xffffffffu, p, o);
    if (lane == 0) out[n] = p + bd2[0];
}

// ---------------- launch ------------------------------------------------------
extern "C" void kernel_launch(void* const* d_in, const int* in_sizes, int n_in,
                              void* d_out, int out_size) {
    const float* x         = (const float*)d_in[0];
    const int*   senders   = (const int*)d_in[1];
    const int*   receivers = (const int*)d_in[2];
    const float* W1a = (const float*)d_in[3];
    const float* b1a = (const float*)d_in[4];
    const float* W2a = (const float*)d_in[5];
    const float* b2a = (const float*)d_in[6];
    const float* W1b = (const float*)d_in[7];
    const float* b1b = (const float*)d_in[8];
    const float* W2b = (const float*)d_in[9];
    const float* b2b = (const float*)d_in[10];
    const float* Wd1 = (const float*)d_in[11];
    const float* bd1 = (const float*)d_in[12];
    const float* Wd2 = (const float*)d_in[13];
    const float* bd2 = (const float*)d_in[14];
    float* out = (float*)d_out;

    static float* pA = nullptr;
    static float* pB = nullptr;
    static float* pAcc = nullptr;
    static int*   pCnt = nullptr;
    static int    nSM = 148;
    if (!pA) {
        cudaGetSymbolAddress((void**)&pA, g_A);
        cudaGetSymbolAddress((void**)&pB, g_B);
        cudaGetSymbolAddress((void**)&pAcc, g_accum);
        cudaGetSymbolAddress((void**)&pCnt, g_cnt);
        cudaFuncSetAttribute(edge_mma_kernel,
                             cudaFuncAttributeMaxDynamicSharedMemorySize,
                             SM_TOTAL);
        cudaDeviceProp prop;
        if (cudaGetDeviceProperties(&prop, 0) == cudaSuccess)
            nSM = prop.multiProcessorCount;
    }

    // CSR build
    zero_cnt_kernel<<<(N_NODES + 255) / 256, 256>>>();
    hist_kernel<<<(N_EDGES + 255) / 256, 256>>>(receivers);
    scan_kernel<<<1, 1024>>>();
    fill_kernel<<<(N_EDGES + 255) / 256, 256>>>(senders, receivers);

    int mmaBlocks = 2 * nSM;

    // Layer 1
    node_ab_kernel<<<N_NODES / 16, 128>>>(x, W1a, b1a, pA, pB, nullptr);
    zero_accum_kernel<<<(N_NODES * 32 + 255) / 256, 256>>>();
    edge_mma_kernel<<<mmaBlocks, 256, SM_TOTAL>>>(pA, pB, W2a, b2a);
    // Layer 2 (mean of layer-1 folded into node_ab read)
    node_ab_kernel<<<N_NODES / 16, 128>>>(pAcc, W1b, b1b, pA, pB, pCnt);
    zero_accum_kernel<<<(N_NODES * 32 + 255) / 256, 256>>>();
    edge_mma_kernel<<<mmaBlocks, 256, SM_TOTAL>>>(pA, pB, W2b, b2b);
    // Dense tail (mean of layer-2 folded in)
    tail_kernel<<<(N_NODES + 7) / 8, 256>>>(pAcc, Wd1, bd1, Wd2, bd2, out, pCnt);
}

// round 12
// speedup vs baseline: 1.9361x; 1.0677x over previous
#include <cuda_runtime.h>
#include <cuda_fp16.h>
#include <cstdint>

// Problem constants
#define N_NODES 50000
#define N_EDGES 800000
#define N_TILES (N_EDGES / 128)     // 6250 exact

// ---------------- scratch (device globals; no allocation allowed) ------------
__device__ int   g_cnt[N_NODES];
__device__ int   g_rowstart[N_NODES + 1];
__device__ int   g_wp[N_NODES];
__device__ int   g_srcs[N_EDGES];          // senders sorted by receiver
__device__ int   g_rcv[N_EDGES];           // receivers sorted (run ids)
__device__ float g_A[N_NODES * 64];        // x @ W1_top + b1
__device__ float g_B[N_NODES * 64];        // x @ W1_bot
__device__ float g_accum[N_NODES * 128];   // segment sums

// ---------------- helpers -----------------------------------------------------
__device__ __forceinline__ uint32_t h2bits(__half2 h) {
    uint32_t u;
    __builtin_memcpy(&u, &h, 4);
    return u;
}
__device__ __forceinline__ void mma_fp16(float* d, const uint32_t* a,
                                         uint32_t b0, uint32_t b1) {
    asm volatile(
        "mma.sync.aligned.m16n8k16.row.col.f32.f16.f16.f32 "
        "{%0,%1,%2,%3}, {%4,%5,%6,%7}, {%8,%9}, {%0,%1,%2,%3};"
        : "+f"(d[0]), "+f"(d[1]), "+f"(d[2]), "+f"(d[3])
        : "r"(a[0]), "r"(a[1]), "r"(a[2]), "r"(a[3]), "r"(b0), "r"(b1));
}
__device__ __forceinline__ unsigned long long pk2(float lo, float hi) {
    unsigned long long r;
    asm("mov.b64 %0, {%1, %2};" : "=l"(r)
        : "r"(__float_as_uint(lo)), "r"(__float_as_uint(hi)));
    return r;
}
__device__ __forceinline__ void upk2(unsigned long long v, float& lo, float& hi) {
    unsigned int a, b;
    asm("mov.b64 {%0, %1}, %2;" : "=r"(a), "=r"(b) : "l"(v));
    lo = __uint_as_float(a);
    hi = __uint_as_float(b);
}
#define FMA2(m, a, b) \
    asm("fma.rn.f32x2 %0, %1, %2, %0;" : "+l"(m) : "l"(a), "l"(b))

// ---------------- CSR construction ------------------------------------------
// Zeros g_cnt AND g_accum (layer-1 prep) in one kernel.
__global__ void zero_kernel() {
    int i = blockIdx.x * blockDim.x + threadIdx.x;
    if (i < N_NODES) g_cnt[i] = 0;
    if (i < N_NODES * 32)
        ((float4*)g_accum)[i] = make_float4(0.f, 0.f, 0.f, 0.f);
}

__global__ void hist_kernel(const int* __restrict__ receivers) {
    int e = blockIdx.x * blockDim.x + threadIdx.x;
    if (e < N_EDGES) atomicAdd(&g_cnt[receivers[e]], 1);
}

__global__ void scan_kernel() {
    __shared__ int wsum[32];
    __shared__ int carry;
    int t = threadIdx.x;
    int lane = t & 31, wid = t >> 5;
    if (t == 0) carry = 0;
    __syncthreads();
    for (int base = 0; base < N_NODES; base += 1024) {
        int i = base + t;
        int v = (i < N_NODES) ? g_cnt[i] : 0;
        int x = v;
#pragma unroll
        for (int o = 1; o < 32; o <<= 1) {
            int y = __shfl_up_sync(0xffffffffu, x, o);
            if (lane >= o) x += y;
        }
        if (lane == 31) wsum[wid] = x;
        __syncthreads();
        if (wid == 0) {
            int s = wsum[lane];
#pragma unroll
            for (int o = 1; o < 32; o <<= 1) {
                int y = __shfl_up_sync(0xffffffffu, s, o);
                if (lane >= o) s += y;
            }
            wsum[lane] = s;
        }
        __syncthreads();
        int excl = carry + (x - v) + (wid > 0 ? wsum[wid - 1] : 0);
        if (i < N_NODES) { g_rowstart[i] = excl; g_wp[i] = excl; }
        __syncthreads();
        if (t == 0) carry += wsum[31];
        __syncthreads();
    }
    if (t == 0) g_rowstart[N_NODES] = carry;
}

__global__ void fill_kernel(const int* __restrict__ senders,
                            const int* __restrict__ receivers) {
    int e = blockIdx.x * blockDim.x + threadIdx.x;
    if (e < N_EDGES) {
        int r = receivers[e];
        int pos = atomicAdd(&g_wp[r], 1);
        g_srcs[pos] = senders[e];
        g_rcv[pos] = r;
    }
}

// ---------------- per-node A/B precompute (FMA2, optional mean-on-read) ------
// When zero_out != null, the block also zeroes the accum rows it just consumed
// (prep for the next edge pass; block-private rows, so race-free).
__global__ __launch_bounds__(128) void node_ab_kernel(
    const float* __restrict__ in, const float* __restrict__ W1,
    const float* __restrict__ b1, float* __restrict__ A, float* __restrict__ B,
    const int* __restrict__ cnt, float* __restrict__ zero_out) {
    __shared__ float xs[16][128];
    int t = threadIdx.x;
    int n0 = blockIdx.x * 16;
    {
        const float4* src = (const float4*)(in + (size_t)n0 * 128);
        float4* dst = (float4*)&xs[0][0];
#pragma unroll
        for (int i = 0; i < 4; i++) {
            int idx = t + i * 128;
            float4 v = src[idx];
            if (cnt) {
                int c = cnt[n0 + (idx >> 5)];
                float inv = (c > 0) ? 1.f / (float)c : 0.f;
                v.x *= inv; v.y *= inv; v.z *= inv; v.w *= inv;
            }
            dst[idx] = v;
        }
    }
    __syncthreads();
    if (zero_out) {
        float4* za = (float4*)(zero_out + (size_t)n0 * 128);
#pragma unroll
        for (int i = 0; i < 4; i++)
            za[t + i * 128] = make_float4(0.f, 0.f, 0.f, 0.f);
    }
    int half = t >> 6, j = t & 63;
    const float* Wb = W1 + half * (128 * 64) + j;
    unsigned long long acc2[16];
#pragma unroll
    for (int nn = 0; nn < 16; nn++) acc2[nn] = 0ull;
#pragma unroll 4
    for (int kp = 0; kp < 64; kp++) {
        float w0 = __ldg(Wb + (2 * kp) * 64);
        float w1 = __ldg(Wb + (2 * kp + 1) * 64);
        unsigned long long ww = pk2(w0, w1);
#pragma unroll
        for (int nn = 0; nn < 16; nn++) {
            unsigned long long xx =
                *(const unsigned long long*)&xs[nn][2 * kp];
            FMA2(acc2[nn], ww, xx);
        }
    }
    float binit = half ? 0.f : b1[j];
    float* out = half ? B : A;
#pragma unroll
    for (int nn = 0; nn < 16; nn++) {
        float lo, hi;
        upk2(acc2[nn], lo, hi);
        out[(size_t)(n0 + nn) * 64 + j] = lo + hi + binit;
    }
}

// ---------------- tensor-core edge kernel (fp16 m16n8k16, 8 warps) ----------
// Tile = 128 edges (M=128), K=64, N=128. Block = 8 warps, 256 threads.
// Warp w: row-group wr = w>>1 owns rows [32wr,32wr+32); col-half w2 = w&1 owns
// cols [64*w2, 64*w2+64). Single-pass epilogue into msg[128][132] (aliases A
// tile). Segmented reduce: thread = (channel-pair q, 32-row segment), float2
// loads; runs touching a segment edge use atomicAdd, interior runs plain store.
#define SM_BFRAG 0          // 2048 uint2 = 16384 B
#define SM_A     16384      // A: 128*36*4 = 18432 B; msg alias: 128*132*4 = 67584 B
#define SM_BIAS  83968      // 512 B
#define SM_RS    84480      // 129 ints = 516 B, ends 84996
#define SM_TOTAL 85120

__global__ void __launch_bounds__(256, 2) edge_mma_kernel(
    const float* __restrict__ Apre, const float* __restrict__ Bpre,
    const float* __restrict__ W2, const float* __restrict__ b2) {
    extern __shared__ char smem[];
    uint32_t* Bfrag = (uint32_t*)(smem + SM_BFRAG);
    uint32_t* As16  = (uint32_t*)(smem + SM_A);
    float* msg  = (float*)(smem + SM_A);
    float* bias = (float*)(smem + SM_BIAS);
    int*   rs   = (int*)(smem + SM_RS);
    int tid = threadIdx.x, w = tid >> 5, lane = tid & 31;
    int wr = w >> 1, w2 = w & 1;

    // Pack W2 (K=64 x N=128) into fp16 fragment order.
    for (int idx = tid; idx < 2048; idx += 256) {
        int nt = idx >> 7;
        int ks = (idx >> 5) & 3;
        int t  = idx & 31;
        int n  = nt * 8 + (t >> 2);
        int k0 = ks * 16 + 2 * (t & 3);
        __half2 p0 = __floats2half2_rn(W2[k0 * 128 + n], W2[(k0 + 1) * 128 + n]);
        __half2 p1 = __floats2half2_rn(W2[(k0 + 8) * 128 + n], W2[(k0 + 9) * 128 + n]);
        Bfrag[idx * 2 + 0] = h2bits(p0);
        Bfrag[idx * 2 + 1] = h2bits(p1);
    }
    if (tid < 128) bias[tid] = b2[tid];
    if (tid == 0) rs[128] = -1;
    __syncthreads();

    const float2* A2 = (const float2*)Apre;
    const float2* B2 = (const float2*)Bpre;
    const uint2*  Bf2 = (const uint2*)Bfrag;

    for (int tile = blockIdx.x; tile < N_TILES; tile += gridDim.x) {
        __syncthreads();   // prev tile's msg/rs fully consumed
        int e0 = tile * 128;
        // ---- build A: warp w builds rows [16w, 16w+16), batched gathers
        int base_e = e0 + w * 16;
        int s_l = g_srcs[base_e + (lane & 15)];
        int r_l = g_rcv[base_e + (lane & 15)];
        if (lane < 16) rs[w * 16 + lane] = r_l;
#pragma unroll
        for (int jb = 0; jb < 16; jb += 8) {
            float2 va[8], vb[8];
#pragma unroll
            for (int j = 0; j < 8; j++) {
                int s = __shfl_sync(0xffffffffu, s_l, jb + j);
                int r = __shfl_sync(0xffffffffu, r_l, jb + j);
                va[j] = A2[(size_t)r * 32 + lane];
                vb[j] = B2[(size_t)s * 32 + lane];
            }
#pragma unroll
            for (int j = 0; j < 8; j++) {
                __half2 h = __floats2half2_rn(fmaxf(va[j].x + vb[j].x, 0.f),
                                              fmaxf(va[j].y + vb[j].y, 0.f));
                As16[(w * 16 + jb + j) * 36 + lane] = h2bits(h);
            }
        }
        __syncthreads();   // all rows built before cross-warp frag reads
        // ---- MMA: warp does rows [32wr,+32) x cols [64w2,+64)
        float d[2][8][4];
#pragma unroll
        for (int mt = 0; mt < 2; mt++)
#pragma unroll
            for (int nt = 0; nt < 8; nt++)
#pragma unroll
                for (int q = 0; q < 4; q++) d[mt][nt][q] = 0.f;
        const uint32_t* abase =
            As16 + (wr * 32 + (lane >> 2)) * 36 + (lane & 3);
        for (int ks = 0; ks < 4; ks++) {
            uint32_t a[2][4];
#pragma unroll
            for (int mt = 0; mt < 2; mt++) {
                const uint32_t* ab = abase + mt * (16 * 36) + ks * 8;
                a[mt][0] = ab[0];
                a[mt][1] = ab[8 * 36];
                a[mt][2] = ab[4];
                a[mt][3] = ab[8 * 36 + 4];
            }
            const uint2* bp = Bf2 + ks * 32 + lane;
#pragma unroll
            for (int ntl = 0; ntl < 8; ntl++) {
                uint2 bb = bp[(w2 * 8 + ntl) * 128];
                mma_fp16(d[0][ntl], a[0], bb.x, bb.y);
                mma_fp16(d[1][ntl], a[1], bb.x, bb.y);
            }
        }
        __syncthreads();   // all warps done reading As before msg overwrites
        // ---- single-pass epilogue: relu(+bias) -> msg[128][132]
#pragma unroll
        for (int mt = 0; mt < 2; mt++) {
            int row = wr * 32 + mt * 16 + (lane >> 2);
#pragma unroll
            for (int ntl = 0; ntl < 8; ntl++) {
                int col = (w2 * 8 + ntl) * 8 + 2 * (lane & 3);
                float2 bv = *(float2*)&bias[col];
                float2 v0, v1;
                v0.x = fmaxf(d[mt][ntl][0] + bv.x, 0.f);
                v0.y = fmaxf(d[mt][ntl][1] + bv.y, 0.f);
                v1.x = fmaxf(d[mt][ntl][2] + bv.x, 0.f);
                v1.y = fmaxf(d[mt][ntl][3] + bv.y, 0.f);
                *(float2*)&msg[row * 132 + col] = v0;
                *(float2*)&msg[(row + 8) * 132 + col] = v1;
            }
        }
        __syncthreads();
        // ---- segmented reduce: 256 threads = 64 channel-pairs x 4 segments
        {
            int q = tid & 63;          // channel pair: cols 2q, 2q+1
            int seg = tid >> 6;        // 4 segments of 32 rows
            int elo = seg * 32, ehi = elo + 32;
            const float2* msg2 = (const float2*)msg;   // row stride 66 float2
            float2 s = make_float2(0.f, 0.f);
            int rstart = elo;
            int cur = rs[elo];
            for (int e = elo; e < ehi; e++) {
                float2 v = msg2[e * 66 + q];
                s.x += v.x; s.y += v.y;
                int nxt = rs[e + 1];     // rs[128] = -1 sentinel
                bool last = (e == ehi - 1) || (nxt != cur);
                if (last) {
                    float* dst = &g_accum[(size_t)cur * 128 + 2 * q];
                    if (rstart == elo || e == ehi - 1) {
                        atomicAdd(dst, s.x);
                        atomicAdd(dst + 1, s.y);
                    } else {
                        *(float2*)dst = s;
                    }
                    s = make_float2(0.f, 0.f);
                    rstart = e + 1;
                    cur = nxt;
                }
            }
        }
    }
}

// ---------------- dense tail (mean folded in) ---------------------------------
__global__ __launch_bounds__(256) void tail_kernel(
    const float* __restrict__ h, const float* __restrict__ Wd1,
    const float* __restrict__ bd1, const float* __restrict__ Wd2,
    const float* __restrict__ bd2, float* __restrict__ out,
    const int* __restrict__ cnt) {
    __shared__ float Ws[128 * 64];
    int t = threadIdx.x;
    {
        const float4* src = (const float4*)Wd1;
        float4* dst = (float4*)Ws;
#pragma unroll
        for (int i = 0; i < 8; i++) dst[t + i * 256] = src[t + i * 256];
    }
    __syncthreads();
    int warp = t >> 5, lane = t & 31;
    int n = blockIdx.x * 8 + warp;
    if (n >= N_NODES) return;
    int c = cnt[n];
    float inv = (c > 0) ? 1.f / (float)c : 0.f;
    float x0 = h[(size_t)n * 128 + lane] * inv;
    float x1 = h[(size_t)n * 128 + 32 + lane] * inv;
    float x2 = h[(size_t)n * 128 + 64 + lane] * inv;
    float x3 = h[(size_t)n * 128 + 96 + lane] * inv;
    float g0 = bd1[lane], g1 = bd1[lane + 32];
#pragma unroll
    for (int kk = 0; kk < 32; kk++) {
        float xk;
        xk = __shfl_sync(0xffffffffu, x0, kk);
        g0 = fmaf(xk, Ws[kk * 64 + lane], g0);
        g1 = fmaf(xk, Ws[kk * 64 + lane + 32], g1);
        xk = __shfl_sync(0xffffffffu, x1, kk);
        g0 = fmaf(xk, Ws[(kk + 32) * 64 + lane], g0);
        g1 = fmaf(xk, Ws[(kk + 32) * 64 + lane + 32], g1);
        xk = __shfl_sync(0xffffffffu, x2, kk);
        g0 = fmaf(xk, Ws[(kk + 64) * 64 + lane], g0);
        g1 = fmaf(xk, Ws[(kk + 64) * 64 + lane + 32], g1);
        xk = __shfl_sync(0xffffffffu, x3, kk);
        g0 = fmaf(xk, Ws[(kk + 96) * 64 + lane], g0);
        g1 = fmaf(xk, Ws[(kk + 96) * 64 + lane + 32], g1);
    }
    g0 = fmaxf(g0, 0.f);
    g1 = fmaxf(g1, 0.f);
    float p = g0 * Wd2[lane] + g1 * Wd2[lane + 32];
#pragma unroll
    for (int o = 16; o > 0; o >>= 1) p += __shfl_xor_sync(0xffffffffu, p, o);
    if (lane == 0) out[n] = p + bd2[0];
}

// ---------------- launch ------------------------------------------------------
extern "C" void kernel_launch(void* const* d_in, const int* in_sizes, int n_in,
                              void* d_out, int out_size) {
    const float* x         = (const float*)d_in[0];
    const int*   senders   = (const int*)d_in[1];
    const int*   receivers = (const int*)d_in[2];
    const float* W1a = (const float*)d_in[3];
    const float* b1a = (const float*)d_in[4];
    const float* W2a = (const float*)d_in[5];
    const float* b2a = (const float*)d_in[6];
    const float* W1b = (const float*)d_in[7];
    const float* b1b = (const float*)d_in[8];
    const float* W2b = (const float*)d_in[9];
    const float* b2b = (const float*)d_in[10];
    const float* Wd1 = (const float*)d_in[11];
    const float* bd1 = (const float*)d_in[12];
    const float* Wd2 = (const float*)d_in[13];
    const float* bd2 = (const float*)d_in[14];
    float* out = (float*)d_out;

    static float* pA = nullptr;
    static float* pB = nullptr;
    static float* pAcc = nullptr;
    static int*   pCnt = nullptr;
    static int    nSM = 148;
    if (!pA) {
        cudaGetSymbolAddress((void**)&pA, g_A);
        cudaGetSymbolAddress((void**)&pB, g_B);
        cudaGetSymbolAddress((void**)&pAcc, g_accum);
        cudaGetSymbolAddress((void**)&pCnt, g_cnt);
        cudaFuncSetAttribute(edge_mma_kernel,
                             cudaFuncAttributeMaxDynamicSharedMemorySize,
                             SM_TOTAL);
        cudaDeviceProp prop;
        if (cudaGetDeviceProperties(&prop, 0) == cudaSuccess)
            nSM = prop.multiProcessorCount;
    }

    // CSR build (zero_kernel also zeroes accum for layer 1)
    zero_kernel<<<(N_NODES * 32 + 255) / 256, 256>>>();
    hist_kernel<<<(N_EDGES + 255) / 256, 256>>>(receivers);
    scan_kernel<<<1, 1024>>>();
    fill_kernel<<<(N_EDGES + 255) / 256, 256>>>(senders, receivers);

    int mmaBlocks = 2 * nSM;

    // Layer 1
    node_ab_kernel<<<N_NODES / 16, 128>>>(x, W1a, b1a, pA, pB, nullptr, nullptr);
    edge_mma_kernel<<<mmaBlocks, 256, SM_TOTAL>>>(pA, pB, W2a, b2a);
    // Layer 2 (mean folded into the accum read; accum re-zeroed in-kernel)
    node_ab_kernel<<<N_NODES / 16, 128>>>(pAcc, W1b, b1b, pA, pB, pCnt, pAcc);
    edge_mma_kernel<<<mmaBlocks, 256, SM_TOTAL>>>(pA, pB, W2b, b2b);
    // Dense tail (mean of layer-2 folded in)
    tail_kernel<<<(N_NODES + 7) / 8, 256>>>(pAcc, Wd1, bd1, Wd2, bd2, out, pCnt);
}

// round 13
// speedup vs baseline: 1.9813x; 1.0234x over previous
#include <cuda_runtime.h>
#include <cuda_fp16.h>
#include <cstdint>

// Problem constants
#define N_NODES 50000
#define N_EDGES 800000
#define N_TILES (N_EDGES / 128)     // 6250 exact

// ---------------- scratch (device globals; no allocation allowed) ------------
__device__ int   g_cnt[N_NODES];
__device__ int   g_rowstart[N_NODES + 1];
__device__ int   g_wp[N_NODES];
__device__ int   g_srcs[N_EDGES];          // senders sorted by receiver
__device__ int   g_rcv[N_EDGES];           // receivers sorted (run ids)
__device__ float g_A[N_NODES * 64];        // x @ W1_top + b1
__device__ float g_B[N_NODES * 64];        // x @ W1_bot
__device__ float g_accum[N_NODES * 128];   // segment sums

// ---------------- helpers -----------------------------------------------------
__device__ __forceinline__ uint32_t h2bits(__half2 h) {
    uint32_t u;
    __builtin_memcpy(&u, &h, 4);
    return u;
}
__device__ __forceinline__ void mma_fp16(float* d, const uint32_t* a,
                                         uint32_t b0, uint32_t b1) {
    asm volatile(
        "mma.sync.aligned.m16n8k16.row.col.f32.f16.f16.f32 "
        "{%0,%1,%2,%3}, {%4,%5,%6,%7}, {%8,%9}, {%0,%1,%2,%3};"
        : "+f"(d[0]), "+f"(d[1]), "+f"(d[2]), "+f"(d[3])
        : "r"(a[0]), "r"(a[1]), "r"(a[2]), "r"(a[3]), "r"(b0), "r"(b1));
}
__device__ __forceinline__ unsigned long long pk2(float lo, float hi) {
    unsigned long long r;
    asm("mov.b64 %0, {%1, %2};" : "=l"(r)
        : "r"(__float_as_uint(lo)), "r"(__float_as_uint(hi)));
    return r;
}
__device__ __forceinline__ void upk2(unsigned long long v, float& lo, float& hi) {
    unsigned int a, b;
    asm("mov.b64 {%0, %1}, %2;" : "=r"(a), "=r"(b) : "l"(v));
    lo = __uint_as_float(a);
    hi = __uint_as_float(b);
}
#define FMA2(m, a, b) \
    asm("fma.rn.f32x2 %0, %1, %2, %0;" : "+l"(m) : "l"(a), "l"(b))

// ---------------- CSR construction ------------------------------------------
// Zeros g_cnt AND g_accum (layer-1 prep) in one kernel.
__global__ void zero_kernel() {
    int i = blockIdx.x * blockDim.x + threadIdx.x;
    if (i < N_NODES) g_cnt[i] = 0;
    if (i < N_NODES * 32)
        ((float4*)g_accum)[i] = make_float4(0.f, 0.f, 0.f, 0.f);
}

__global__ void hist_kernel(const int* __restrict__ receivers) {
    int e = blockIdx.x * blockDim.x + threadIdx.x;
    if (e < N_EDGES) atomicAdd(&g_cnt[receivers[e]], 1);
}

__global__ void scan_kernel() {
    __shared__ int wsum[32];
    __shared__ int carry;
    int t = threadIdx.x;
    int lane = t & 31, wid = t >> 5;
    if (t == 0) carry = 0;
    __syncthreads();
    for (int base = 0; base < N_NODES; base += 1024) {
        int i = base + t;
        int v = (i < N_NODES) ? g_cnt[i] : 0;
        int x = v;
#pragma unroll
        for (int o = 1; o < 32; o <<= 1) {
            int y = __shfl_up_sync(0xffffffffu, x, o);
            if (lane >= o) x += y;
        }
        if (lane == 31) wsum[wid] = x;
        __syncthreads();
        if (wid == 0) {
            int s = wsum[lane];
#pragma unroll
            for (int o = 1; o < 32; o <<= 1) {
                int y = __shfl_up_sync(0xffffffffu, s, o);
                if (lane >= o) s += y;
            }
            wsum[lane] = s;
        }
        __syncthreads();
        int excl = carry + (x - v) + (wid > 0 ? wsum[wid - 1] : 0);
        if (i < N_NODES) { g_rowstart[i] = excl; g_wp[i] = excl; }
        __syncthreads();
        if (t == 0) carry += wsum[31];
        __syncthreads();
    }
    if (t == 0) g_rowstart[N_NODES] = carry;
}

__global__ void fill_kernel(const int* __restrict__ senders,
                            const int* __restrict__ receivers) {
    int e = blockIdx.x * blockDim.x + threadIdx.x;
    if (e < N_EDGES) {
        int r = receivers[e];
        int pos = atomicAdd(&g_wp[r], 1);
        g_srcs[pos] = senders[e];
        g_rcv[pos] = r;
    }
}

// ---------------- per-node A/B precompute (FMA2, optional mean-on-read) ------
__global__ __launch_bounds__(128) void node_ab_kernel(
    const float* __restrict__ in, const float* __restrict__ W1,
    const float* __restrict__ b1, float* __restrict__ A, float* __restrict__ B,
    const int* __restrict__ cnt, float* __restrict__ zero_out) {
    __shared__ float xs[16][128];
    int t = threadIdx.x;
    int n0 = blockIdx.x * 16;
    {
        const float4* src = (const float4*)(in + (size_t)n0 * 128);
        float4* dst = (float4*)&xs[0][0];
#pragma unroll
        for (int i = 0; i < 4; i++) {
            int idx = t + i * 128;
            float4 v = src[idx];
            if (cnt) {
                int c = cnt[n0 + (idx >> 5)];
                float inv = (c > 0) ? 1.f / (float)c : 0.f;
                v.x *= inv; v.y *= inv; v.z *= inv; v.w *= inv;
            }
            dst[idx] = v;
        }
    }
    __syncthreads();
    if (zero_out) {
        float4* za = (float4*)(zero_out + (size_t)n0 * 128);
#pragma unroll
        for (int i = 0; i < 4; i++)
            za[t + i * 128] = make_float4(0.f, 0.f, 0.f, 0.f);
    }
    int half = t >> 6, j = t & 63;
    const float* Wb = W1 + half * (128 * 64) + j;
    unsigned long long acc2[16];
#pragma unroll
    for (int nn = 0; nn < 16; nn++) acc2[nn] = 0ull;
#pragma unroll 4
    for (int kp = 0; kp < 64; kp++) {
        float w0 = __ldg(Wb + (2 * kp) * 64);
        float w1 = __ldg(Wb + (2 * kp + 1) * 64);
        unsigned long long ww = pk2(w0, w1);
#pragma unroll
        for (int nn = 0; nn < 16; nn++) {
            unsigned long long xx =
                *(const unsigned long long*)&xs[nn][2 * kp];
            FMA2(acc2[nn], ww, xx);
        }
    }
    float binit = half ? 0.f : b1[j];
    float* out = half ? B : A;
#pragma unroll
    for (int nn = 0; nn < 16; nn++) {
        float lo, hi;
        upk2(acc2[nn], lo, hi);
        out[(size_t)(n0 + nn) * 64 + j] = lo + hi + binit;
    }
}

// ---------------- tensor-core edge kernel (fp16 m16n8k16, 8 warps) ----------
// Tile = 128 edges (M=128), K=64, N=128. Block = 8 warps, 256 threads,
// 3 blocks/SM (msg now fp16x2 -> smem 51.5 KB). Warp w: row-group wr = w>>1,
// col-half w2 = w&1. Single-pass epilogue into msg[128][66 half2] (aliases A
// tile). Segmented reduce: thread = (channel-pair q, 32-row segment), half2
// loads converted to fp32; segment-edge runs atomicAdd, interior plain store.
#define SM_BFRAG 0          // 2048 uint2 = 16384 B
#define SM_A     16384      // A: 128*36*4 = 18432 B; msg alias: 128*66*4 = 33792 B
#define SM_BIAS  50176      // 512 B
#define SM_RS    50688      // 129 ints = 516 B, ends 51204
#define SM_TOTAL 51456

__global__ void __launch_bounds__(256, 3) edge_mma_kernel(
    const float* __restrict__ Apre, const float* __restrict__ Bpre,
    const float* __restrict__ W2, const float* __restrict__ b2) {
    extern __shared__ char smem[];
    uint32_t* Bfrag = (uint32_t*)(smem + SM_BFRAG);
    uint32_t* As16  = (uint32_t*)(smem + SM_A);
    __half2* msgh   = (__half2*)(smem + SM_A);
    float* bias = (float*)(smem + SM_BIAS);
    int*   rs   = (int*)(smem + SM_RS);
    int tid = threadIdx.x, w = tid >> 5, lane = tid & 31;
    int wr = w >> 1, w2 = w & 1;

    // Pack W2 (K=64 x N=128) into fp16 fragment order.
    for (int idx = tid; idx < 2048; idx += 256) {
        int nt = idx >> 7;
        int ks = (idx >> 5) & 3;
        int t  = idx & 31;
        int n  = nt * 8 + (t >> 2);
        int k0 = ks * 16 + 2 * (t & 3);
        __half2 p0 = __floats2half2_rn(W2[k0 * 128 + n], W2[(k0 + 1) * 128 + n]);
        __half2 p1 = __floats2half2_rn(W2[(k0 + 8) * 128 + n], W2[(k0 + 9) * 128 + n]);
        Bfrag[idx * 2 + 0] = h2bits(p0);
        Bfrag[idx * 2 + 1] = h2bits(p1);
    }
    if (tid < 128) bias[tid] = b2[tid];
    if (tid == 0) rs[128] = -1;
    __syncthreads();

    const float2* A2 = (const float2*)Apre;
    const float2* B2 = (const float2*)Bpre;
    const uint2*  Bf2 = (const uint2*)Bfrag;

    for (int tile = blockIdx.x; tile < N_TILES; tile += gridDim.x) {
        __syncthreads();   // prev tile's msg/rs fully consumed
        int e0 = tile * 128;
        // ---- build A: warp w builds rows [16w, 16w+16), batched gathers
        int base_e = e0 + w * 16;
        int s_l = g_srcs[base_e + (lane & 15)];
        int r_l = g_rcv[base_e + (lane & 15)];
        if (lane < 16) rs[w * 16 + lane] = r_l;
#pragma unroll
        for (int jb = 0; jb < 16; jb += 8) {
            float2 va[8], vb[8];
#pragma unroll
            for (int j = 0; j < 8; j++) {
                int s = __shfl_sync(0xffffffffu, s_l, jb + j);
                int r = __shfl_sync(0xffffffffu, r_l, jb + j);
                va[j] = A2[(size_t)r * 32 + lane];
                vb[j] = B2[(size_t)s * 32 + lane];
            }
#pragma unroll
            for (int j = 0; j < 8; j++) {
                __half2 h = __floats2half2_rn(fmaxf(va[j].x + vb[j].x, 0.f),
                                              fmaxf(va[j].y + vb[j].y, 0.f));
                As16[(w * 16 + jb + j) * 36 + lane] = h2bits(h);
            }
        }
        __syncthreads();   // all rows built before cross-warp frag reads
        // ---- MMA: warp does rows [32wr,+32) x cols [64w2,+64)
        float d[2][8][4];
#pragma unroll
        for (int mt = 0; mt < 2; mt++)
#pragma unroll
            for (int nt = 0; nt < 8; nt++)
#pragma unroll
                for (int q = 0; q < 4; q++) d[mt][nt][q] = 0.f;
        const uint32_t* abase =
            As16 + (wr * 32 + (lane >> 2)) * 36 + (lane & 3);
        for (int ks = 0; ks < 4; ks++) {
            uint32_t a[2][4];
#pragma unroll
            for (int mt = 0; mt < 2; mt++) {
                const uint32_t* ab = abase + mt * (16 * 36) + ks * 8;
                a[mt][0] = ab[0];
                a[mt][1] = ab[8 * 36];
                a[mt][2] = ab[4];
                a[mt][3] = ab[8 * 36 + 4];
            }
            const uint2* bp = Bf2 + ks * 32 + lane;
#pragma unroll
            for (int ntl = 0; ntl < 8; ntl++) {
                uint2 bb = bp[(w2 * 8 + ntl) * 128];
                mma_fp16(d[0][ntl], a[0], bb.x, bb.y);
                mma_fp16(d[1][ntl], a[1], bb.x, bb.y);
            }
        }
        __syncthreads();   // all warps done reading As before msg overwrites
        // ---- single-pass epilogue: relu(+bias) -> msg fp16x2 [128][66]
#pragma unroll
        for (int mt = 0; mt < 2; mt++) {
            int row = wr * 32 + mt * 16 + (lane >> 2);
#pragma unroll
            for (int ntl = 0; ntl < 8; ntl++) {
                int col  = (w2 * 8 + ntl) * 8 + 2 * (lane & 3);
                int colh = col >> 1;
                float2 bv = *(float2*)&bias[col];
                msgh[row * 66 + colh] = __floats2half2_rn(
                    fmaxf(d[mt][ntl][0] + bv.x, 0.f),
                    fmaxf(d[mt][ntl][1] + bv.y, 0.f));
                msgh[(row + 8) * 66 + colh] = __floats2half2_rn(
                    fmaxf(d[mt][ntl][2] + bv.x, 0.f),
                    fmaxf(d[mt][ntl][3] + bv.y, 0.f));
            }
        }
        __syncthreads();
        // ---- segmented reduce: 256 threads = 64 channel-pairs x 4 segments
        {
            int q = tid & 63;          // channel pair: cols 2q, 2q+1
            int seg = tid >> 6;        // 4 segments of 32 rows
            int elo = seg * 32, ehi = elo + 32;
            float2 s = make_float2(0.f, 0.f);
            int rstart = elo;
            int cur = rs[elo];
            for (int e = elo; e < ehi; e++) {
                float2 v = __half22float2(msgh[e * 66 + q]);
                s.x += v.x; s.y += v.y;
                int nxt = rs[e + 1];     // rs[128] = -1 sentinel
                bool last = (e == ehi - 1) || (nxt != cur);
                if (last) {
                    float* dst = &g_accum[(size_t)cur * 128 + 2 * q];
                    if (rstart == elo || e == ehi - 1) {
                        atomicAdd(dst, s.x);
                        atomicAdd(dst + 1, s.y);
                    } else {
                        *(float2*)dst = s;
                    }
                    s = make_float2(0.f, 0.f);
                    rstart = e + 1;
                    cur = nxt;
                }
            }
        }
    }
}

// ---------------- dense tail (mean folded in) ---------------------------------
__global__ __launch_bounds__(256) void tail_kernel(
    const float* __restrict__ h, const float* __restrict__ Wd1,
    const float* __restrict__ bd1, const float* __restrict__ Wd2,
    const float* __restrict__ bd2, float* __restrict__ out,
    const int* __restrict__ cnt) {
    __shared__ float Ws[128 * 64];
    int t = threadIdx.x;
    {
        const float4* src = (const float4*)Wd1;
        float4* dst = (float4*)Ws;
#pragma unroll
        for (int i = 0; i < 8; i++) dst[t + i * 256] = src[t + i * 256];
    }
    __syncthreads();
    int warp = t >> 5, lane = t & 31;
    int n = blockIdx.x * 8 + warp;
    if (n >= N_NODES) return;
    int c = cnt[n];
    float inv = (c > 0) ? 1.f / (float)c : 0.f;
    float x0 = h[(size_t)n * 128 + lane] * inv;
    float x1 = h[(size_t)n * 128 + 32 + lane] * inv;
    float x2 = h[(size_t)n * 128 + 64 + lane] * inv;
    float x3 = h[(size_t)n * 128 + 96 + lane] * inv;
    float g0 = bd1[lane], g1 = bd1[lane + 32];
#pragma unroll
    for (int kk = 0; kk < 32; kk++) {
        float xk;
        xk = __shfl_sync(0xffffffffu, x0, kk);
        g0 = fmaf(xk, Ws[kk * 64 + lane], g0);
        g1 = fmaf(xk, Ws[kk * 64 + lane + 32], g1);
        xk = __shfl_sync(0xffffffffu, x1, kk);
        g0 = fmaf(xk, Ws[(kk + 32) * 64 + lane], g0);
        g1 = fmaf(xk, Ws[(kk + 32) * 64 + lane + 32], g1);
        xk = __shfl_sync(0xffffffffu, x2, kk);
        g0 = fmaf(xk, Ws[(kk + 64) * 64 + lane], g0);
        g1 = fmaf(xk, Ws[(kk + 64) * 64 + lane + 32], g1);
        xk = __shfl_sync(0xffffffffu, x3, kk);
        g0 = fmaf(xk, Ws[(kk + 96) * 64 + lane], g0);
        g1 = fmaf(xk, Ws[(kk + 96) * 64 + lane + 32], g1);
    }
    g0 = fmaxf(g0, 0.f);
    g1 = fmaxf(g1, 0.f);
    float p = g0 * Wd2[lane] + g1 * Wd2[lane + 32];
#pragma unroll
    for (int o = 16; o > 0; o >>= 1) p += __shfl_xor_sync(0xffffffffu, p, o);
    if (lane == 0) out[n] = p + bd2[0];
}

// ---------------- launch ------------------------------------------------------
extern "C" void kernel_launch(void* const* d_in, const int* in_sizes, int n_in,
                              void* d_out, int out_size) {
    const float* x         = (const float*)d_in[0];
    const int*   senders   = (const int*)d_in[1];
    const int*   receivers = (const int*)d_in[2];
    const float* W1a = (const float*)d_in[3];
    const float* b1a = (const float*)d_in[4];
    const float* W2a = (const float*)d_in[5];
    const float* b2a = (const float*)d_in[6];
    const float* W1b = (const float*)d_in[7];
    const float* b1b = (const float*)d_in[8];
    const float* W2b = (const float*)d_in[9];
    const float* b2b = (const float*)d_in[10];
    const float* Wd1 = (const float*)d_in[11];
    const float* bd1 = (const float*)d_in[12];
    const float* Wd2 = (const float*)d_in[13];
    const float* bd2 = (const float*)d_in[14];
    float* out = (float*)d_out;

    static float* pA = nullptr;
    static float* pB = nullptr;
    static float* pAcc = nullptr;
    static int*   pCnt = nullptr;
    static int    nSM = 148;
    if (!pA) {
        cudaGetSymbolAddress((void**)&pA, g_A);
        cudaGetSymbolAddress((void**)&pB, g_B);
        cudaGetSymbolAddress((void**)&pAcc, g_accum);
        cudaGetSymbolAddress((void**)&pCnt, g_cnt);
        cudaFuncSetAttribute(edge_mma_kernel,
                             cudaFuncAttributeMaxDynamicSharedMemorySize,
                             SM_TOTAL);
        cudaDeviceProp prop;
        if (cudaGetDeviceProperties(&prop, 0) == cudaSuccess)
            nSM = prop.multiProcessorCount;
    }

    // CSR build (zero_kernel also zeroes accum for layer 1)
    zero_kernel<<<(N_NODES * 32 + 255) / 256, 256>>>();
    hist_kernel<<<(N_EDGES + 255) / 256, 256>>>(receivers);
    scan_kernel<<<1, 1024>>>();
    fill_kernel<<<(N_EDGES + 255) / 256, 256>>>(senders, receivers);

    int mmaBlocks = 3 * nSM;

    // Layer 1
    node_ab_kernel<<<N_NODES / 16, 128>>>(x, W1a, b1a, pA, pB, nullptr, nullptr);
    edge_mma_kernel<<<mmaBlocks, 256, SM_TOTAL>>>(pA, pB, W2a, b2a);
    // Layer 2 (mean folded into the accum read; accum re-zeroed in-kernel)
    node_ab_kernel<<<N_NODES / 16, 128>>>(pAcc, W1b, b1b, pA, pB, pCnt, pAcc);
    edge_mma_kernel<<<mmaBlocks, 256, SM_TOTAL>>>(pA, pB, W2b, b2b);
    // Dense tail (mean of layer-2 folded in)
    tail_kernel<<<(N_NODES + 7) / 8, 256>>>(pAcc, Wd1, bd1, Wd2, bd2, out, pCnt);
}